// round 9
// baseline (speedup 1.0000x reference)
#include <cuda_runtime.h>
#include <cuda_fp16.h>
#include <mma.h>
#include <math.h>
#include <stdint.h>

using namespace nvcuda;

#define T  1024
#define Hd 1024
#define Fd 2048
#define Ed 8

#define BM 128
#define BN 64
#define BK 32                  // halves per stage; 64B data per row
#define KP 40                  // BK + 8 pad halves -> 80B rows
#define RB 80
#define A_BYTES (BM * RB)      // 10240
#define B_BYTES (BN * RB)      // 5120
#define NSTAGE 3
#define OPAD 68

#define F1_A   1024
#define F1_B1  (F1_A  + NSTAGE * A_BYTES)
#define F1_B3  (F1_B1 + NSTAGE * B_BYTES)
#define SMEM_FFN1 (F1_B3 + NSTAGE * B_BYTES)   // 62464
#define F2_A   1024
#define F2_B   (F2_A + NSTAGE * A_BYTES)
#define SMEM_FFN2 (F2_B + NSTAGE * B_BYTES)    // 47104

// ---------------- scratch ----------------
__device__ __half g_interh[(size_t)Ed * T * Fd];         // 32 MB
__device__ __half g_xh[(size_t)T * Hd];                  // 2 MB
__device__ int   g_tok[Ed * T];
__device__ float g_pw[Ed * T];
__device__ int   g_cnt[Ed];
__device__ int   g_sel[T * 2];
__device__ float g_mult[T * 2];

__device__ __forceinline__ uint32_t f2h2(float x, float y) {
    __half2 h = __floats2half2_rn(x, y);
    return *(uint32_t*)&h;
}
// fp32x8 -> fp16x8 packed
__device__ __forceinline__ uint4 ldg_cvt8(const float* g) {
    float4 lo = __ldg((const float4*)g);
    float4 hi = __ldg((const float4*)(g + 4));
    uint4 o;
    o.x = f2h2(lo.x, lo.y); o.y = f2h2(lo.z, lo.w);
    o.z = f2h2(hi.x, hi.y); o.w = f2h2(hi.z, hi.w);
    return o;
}
__device__ __forceinline__ void cp16(void* s, const void* g) {
    unsigned a = (unsigned)__cvta_generic_to_shared(s);
    asm volatile("cp.async.cg.shared.global [%0], [%1], 16;" :: "r"(a), "l"(g));
}
#define CP_COMMIT() asm volatile("cp.async.commit_group;" ::)
#define CP_WAIT1()  asm volatile("cp.async.wait_group 1;" ::)

// ---------------- kernel 0: zero output + counters ----------------
__global__ void zero_kernel(float* __restrict__ out) {
    int i = blockIdx.x * 256 + threadIdx.x;
    out[i] = 0.0f;
    if (i < Ed) g_cnt[i] = 0;
}

// ---------------- kernel 0b: x fp32 -> fp16 (8 floats/thread) --------------
__global__ __launch_bounds__(256) void cvt_h_kernel(const float4* __restrict__ src,
                                                    uint4* __restrict__ dst) {
    size_t i = (size_t)blockIdx.x * 256 + threadIdx.x;
    float4 a = src[2 * i];
    float4 b = src[2 * i + 1];
    uint4 o;
    o.x = f2h2(a.x, a.y); o.y = f2h2(a.z, a.w);
    o.z = f2h2(b.x, b.y); o.w = f2h2(b.z, b.w);
    dst[i] = o;
}

// ---------------- kernel 1: router (fp32) ----------------
__global__ __launch_bounds__(256) void router_kernel(
    const float* __restrict__ x, const float* __restrict__ gw,
    float* __restrict__ out_logits, int write_logits)
{
    int t = blockIdx.x, warp = threadIdx.x >> 5, lane = threadIdx.x & 31;
    const float* xr = x + (size_t)t * Hd;
    const float* gr = gw + (size_t)warp * Hd;
    float s = 0.0f;
    for (int h = lane; h < Hd; h += 32) s += xr[h] * gr[h];
    #pragma unroll
    for (int o = 16; o; o >>= 1) s += __shfl_xor_sync(0xFFFFFFFFu, s, o);

    __shared__ float sc[Ed];
    if (lane == 0) sc[warp] = s;
    __syncthreads();
    if (threadIdx.x < Ed && write_logits) out_logits[t * Ed + threadIdx.x] = sc[threadIdx.x];

    if (threadIdx.x == 0) {
        float v[Ed];
        #pragma unroll
        for (int e = 0; e < Ed; e++) v[e] = sc[e];
        int s1 = 0; float m1 = v[0];
        #pragma unroll
        for (int e = 1; e < Ed; e++) if (v[e] > m1) { m1 = v[e]; s1 = e; }
        float Z1 = 0.0f;
        #pragma unroll
        for (int e = 0; e < Ed; e++) {
            float factor = fmaxf(fabsf(v[e]), m1);
            if (!((m1 - v[e]) / factor > 0.02f)) Z1 += expf(v[e] - m1);
        }
        int s2 = -1; float m2 = -INFINITY;
        #pragma unroll
        for (int e = 0; e < Ed; e++) if (e != s1 && v[e] > m2) { m2 = v[e]; s2 = e; }
        float Z2 = 0.0f;
        #pragma unroll
        for (int e = 0; e < Ed; e++) {
            if (e == s1) continue;
            float factor = fmaxf(fabsf(v[e]), m2);
            if (!((m2 - v[e]) / factor > 0.02f)) Z2 += expf(v[e] - m2);
        }
        g_sel [t * 2 + 0] = s1;        g_sel [t * 2 + 1] = s2;
        g_mult[t * 2 + 0] = 1.0f / Z1; g_mult[t * 2 + 1] = 1.0f / Z2;
    }
}

// ---------------- kernel 2: scatter ----------------
__global__ void scatter_kernel() {
    int t = blockIdx.x * 256 + threadIdx.x;
    if (t >= T) return;
    #pragma unroll
    for (int k = 0; k < 2; k++) {
        int e = g_sel[t * 2 + k];
        int p = atomicAdd(&g_cnt[e], 1);
        g_tok[e * T + p] = t;
        g_pw [e * T + p] = g_mult[t * 2 + k];
    }
}

// ---------------- kernel 3: ffn1 (fp16 wmma; B converted inline) -----------
// grid (Fd/BN=32, Ed*8=64), 256 threads (8 warps, 4m x 2n), warp 32x32 dual
__global__ __launch_bounds__(256, 2) void ffn1_kernel(
    const float* __restrict__ w1, const float* __restrict__ w3)
{
    extern __shared__ char sm[];
    int e   = blockIdx.y >> 3;
    int mt  = blockIdx.y & 7;
    int cnt = g_cnt[e];
    int m0  = mt * BM;
    if (m0 >= cnt) return;
    int f0  = blockIdx.x * BN;

    int* toks = (int*)sm;
    int tid = threadIdx.x;
    if (tid < BM) {
        int i = m0 + tid;
        toks[tid] = (i < cnt) ? g_tok[e * T + i] : g_tok[e * T];
    }
    __syncthreads();

    int ar0 = tid >> 2;                  // 0..63
    int aqh = (tid & 3) * 8;             // chunk offset (8 elements)
    uint32_t soA0 = (uint32_t)ar0 * RB + (tid & 3) * 16;
    uint32_t soA1 = soA0 + 64 * RB;
    uint32_t soB  = soA0;

    const float* w1e = w1 + (size_t)e * Fd * Hd;
    const float* w3e = w3 + (size_t)e * Fd * Hd;
    const __half* ag0 = g_xh + (size_t)toks[ar0]      * Hd + aqh;
    const __half* ag1 = g_xh + (size_t)toks[ar0 + 64] * Hd + aqh;
    const float* b1g = w1e + (size_t)(f0 + ar0) * Hd + aqh;
    const float* b3g = w3e + (size_t)(f0 + ar0) * Hd + aqh;

    char* smA  = sm + F1_A;
    char* smB1 = sm + F1_B1;
    char* smB3 = sm + F1_B3;

    const int NS = Hd / BK;   // 32
    // prologue: A cp.async stages 0,1; B direct-store stages 0,1; B regs stage 2
    #pragma unroll
    for (int s = 0; s < NSTAGE - 1; s++) {
        int k0 = s * BK;
        cp16(smA + s * A_BYTES + soA0, ag0 + k0);
        cp16(smA + s * A_BYTES + soA1, ag1 + k0);
        CP_COMMIT();
        *(uint4*)(smB1 + s * B_BYTES + soB) = ldg_cvt8(b1g + k0);
        *(uint4*)(smB3 + s * B_BYTES + soB) = ldg_cvt8(b3g + k0);
    }
    uint4 b1r = ldg_cvt8(b1g + 2 * BK);
    uint4 b3r = ldg_cvt8(b3g + 2 * BK);

    wmma::fragment<wmma::matrix_a, 16,16,16, __half, wmma::row_major> fa[2];
    wmma::fragment<wmma::matrix_b, 16,16,16, __half, wmma::col_major> fb1[2], fb3[2];
    wmma::fragment<wmma::accumulator, 16,16,16, float> acc1[2][2], acc3[2][2];
    #pragma unroll
    for (int i = 0; i < 2; i++)
        #pragma unroll
        for (int j = 0; j < 2; j++) { wmma::fill_fragment(acc1[i][j], 0.f); wmma::fill_fragment(acc3[i][j], 0.f); }

    int wid = tid >> 5;
    int wm  = wid >> 1;     // 0..3
    int wn  = wid & 1;      // 0..1

    int cur = 0;
    for (int s = 0; s < NS; s++) {
        CP_WAIT1();
        __syncthreads();
        if (s + 2 < NS) {
            int b2 = (s + 2) % NSTAGE;
            int k0 = (s + 2) * BK;
            cp16(smA + b2 * A_BYTES + soA0, ag0 + k0);
            cp16(smA + b2 * A_BYTES + soA1, ag1 + k0);
            // store B regs (stage s+2), then prefetch stage s+3
            *(uint4*)(smB1 + b2 * B_BYTES + soB) = b1r;
            *(uint4*)(smB3 + b2 * B_BYTES + soB) = b3r;
            if (s + 3 < NS) {
                b1r = ldg_cvt8(b1g + (s + 3) * BK);
                b3r = ldg_cvt8(b3g + (s + 3) * BK);
            }
        }
        CP_COMMIT();

        const __half* Ab  = (const __half*)(smA  + cur * A_BYTES);
        const __half* B1b = (const __half*)(smB1 + cur * B_BYTES);
        const __half* B3b = (const __half*)(smB3 + cur * B_BYTES);
        #pragma unroll
        for (int ks = 0; ks < BK; ks += 16) {
            wmma::load_matrix_sync(fa[0],  Ab  + (wm*32     ) * KP + ks, KP);
            wmma::load_matrix_sync(fa[1],  Ab  + (wm*32 + 16) * KP + ks, KP);
            wmma::load_matrix_sync(fb1[0], B1b + (wn*32     ) * KP + ks, KP);
            wmma::load_matrix_sync(fb1[1], B1b + (wn*32 + 16) * KP + ks, KP);
            wmma::load_matrix_sync(fb3[0], B3b + (wn*32     ) * KP + ks, KP);
            wmma::load_matrix_sync(fb3[1], B3b + (wn*32 + 16) * KP + ks, KP);
            #pragma unroll
            for (int i = 0; i < 2; i++)
                #pragma unroll
                for (int j = 0; j < 2; j++) {
                    wmma::mma_sync(acc1[i][j], fa[i], fb1[j], acc1[i][j]);
                    wmma::mma_sync(acc3[i][j], fa[i], fb3[j], acc3[i][j]);
                }
        }
        cur = (cur + 1 == NSTAGE) ? 0 : cur + 1;
    }

    // epilogue: silu(h1)*h3, stage f32 in smem, emit half2 to g_interh
    __syncthreads();
    float* pool = (float*)(sm + F1_A);
    #pragma unroll
    for (int i = 0; i < 2; i++)
        #pragma unroll
        for (int j = 0; j < 2; j++) {
            #pragma unroll
            for (int el = 0; el < acc1[i][j].num_elements; el++) {
                float h1 = acc1[i][j].x[el], h3 = acc3[i][j].x[el];
                acc1[i][j].x[el] = h1 / (1.0f + expf(-h1)) * h3;
            }
            wmma::store_matrix_sync(
                pool + (size_t)(wm*32 + i*16) * OPAD + wn*32 + j*16,
                acc1[i][j], OPAD, wmma::mem_row_major);
        }
    __syncthreads();

    for (int idx = tid; idx < BM * BN / 2; idx += 256) {
        int r  = idx >> 5;
        int c2 = idx & 31;
        uint32_t h = f2h2(pool[r * OPAD + 2*c2], pool[r * OPAD + 2*c2 + 1]);
        *(uint32_t*)&g_interh[((size_t)e * T + m0 + r) * Fd + f0 + 2*c2] = h;
    }
}

// ---------------- kernel 4: ffn2 (fp16 wmma; w2 converted inline) -----------
// grid (Hd/BN=16, Ed*8=64), 256 threads, warp 32x32
__global__ __launch_bounds__(256, 2) void ffn2_kernel(
    const float* __restrict__ w2, float* __restrict__ out)
{
    extern __shared__ char sm[];
    int e   = blockIdx.y >> 3;
    int mt  = blockIdx.y & 7;
    int cnt = g_cnt[e];
    int m0  = mt * BM;
    if (m0 >= cnt) return;
    int h0  = blockIdx.x * BN;

    int*   toks = (int*)sm;
    float* pws  = (float*)(sm + 512);
    int tid = threadIdx.x;
    if (tid < BM) {
        int i = m0 + tid;
        toks[tid] = (i < cnt) ? g_tok[e * T + i] : 0;
        pws [tid] = (i < cnt) ? g_pw [e * T + i] : 0.0f;
    }
    __syncthreads();

    int ar0 = tid >> 2;
    int aqh = (tid & 3) * 8;
    uint32_t soA0 = (uint32_t)ar0 * RB + (tid & 3) * 16;
    uint32_t soA1 = soA0 + 64 * RB;
    uint32_t soB  = soA0;

    const __half* ag0 = &g_interh[((size_t)e * T + m0 + ar0     ) * Fd + aqh];
    const __half* ag1 = &g_interh[((size_t)e * T + m0 + ar0 + 64) * Fd + aqh];
    const float*  bg  = w2 + ((size_t)e * Hd + h0 + ar0) * Fd + aqh;

    char* smA = sm + F2_A;
    char* smB = sm + F2_B;

    const int NS = Fd / BK;   // 64
    #pragma unroll
    for (int s = 0; s < NSTAGE - 1; s++) {
        int k0 = s * BK;
        cp16(smA + s * A_BYTES + soA0, ag0 + k0);
        cp16(smA + s * A_BYTES + soA1, ag1 + k0);
        CP_COMMIT();
        *(uint4*)(smB + s * B_BYTES + soB) = ldg_cvt8(bg + k0);
    }
    uint4 br = ldg_cvt8(bg + 2 * BK);

    wmma::fragment<wmma::matrix_a, 16,16,16, __half, wmma::row_major> fa[2];
    wmma::fragment<wmma::matrix_b, 16,16,16, __half, wmma::col_major> fb[2];
    wmma::fragment<wmma::accumulator, 16,16,16, float> acc[2][2];
    #pragma unroll
    for (int i = 0; i < 2; i++)
        #pragma unroll
        for (int j = 0; j < 2; j++) wmma::fill_fragment(acc[i][j], 0.f);

    int wid = tid >> 5;
    int wm  = wid >> 1;
    int wn  = wid & 1;

    int cur = 0;
    for (int s = 0; s < NS; s++) {
        CP_WAIT1();
        __syncthreads();
        if (s + 2 < NS) {
            int b2 = (s + 2) % NSTAGE;
            int k0 = (s + 2) * BK;
            cp16(smA + b2 * A_BYTES + soA0, ag0 + k0);
            cp16(smA + b2 * A_BYTES + soA1, ag1 + k0);
            *(uint4*)(smB + b2 * B_BYTES + soB) = br;
            if (s + 3 < NS) br = ldg_cvt8(bg + (s + 3) * BK);
        }
        CP_COMMIT();

        const __half* Ab = (const __half*)(smA + cur * A_BYTES);
        const __half* Bb = (const __half*)(smB + cur * B_BYTES);
        #pragma unroll
        for (int ks = 0; ks < BK; ks += 16) {
            wmma::load_matrix_sync(fa[0], Ab + (wm*32     ) * KP + ks, KP);
            wmma::load_matrix_sync(fa[1], Ab + (wm*32 + 16) * KP + ks, KP);
            wmma::load_matrix_sync(fb[0], Bb + (wn*32     ) * KP + ks, KP);
            wmma::load_matrix_sync(fb[1], Bb + (wn*32 + 16) * KP + ks, KP);
            #pragma unroll
            for (int i = 0; i < 2; i++)
                #pragma unroll
                for (int j = 0; j < 2; j++)
                    wmma::mma_sync(acc[i][j], fa[i], fb[j], acc[i][j]);
        }
        cur = (cur + 1 == NSTAGE) ? 0 : cur + 1;
    }

    __syncthreads();
    float* pool = (float*)(sm + F2_A);
    #pragma unroll
    for (int i = 0; i < 2; i++)
        #pragma unroll
        for (int j = 0; j < 2; j++)
            wmma::store_matrix_sync(
                pool + (size_t)(wm*32 + i*16) * OPAD + wn*32 + j*16,
                acc[i][j], OPAD, wmma::mem_row_major);
    __syncthreads();

    for (int idx = tid; idx < BM * BN; idx += 256) {
        int r = idx >> 6;
        int c = idx & 63;
        if (m0 + r < cnt)
            atomicAdd(&out[(size_t)toks[r] * Hd + h0 + c], pws[r] * pool[r * OPAD + c]);
    }
}

// ---------------- launch ----------------
extern "C" void kernel_launch(void* const* d_in, const int* in_sizes, int n_in,
                              void* d_out, int out_size)
{
    const float* x  = (const float*)d_in[0];
    const float* gw = (const float*)d_in[1];
    const float* w1 = (const float*)d_in[2];
    const float* w2 = (const float*)d_in[3];
    const float* w3 = (const float*)d_in[4];
    float* out = (float*)d_out;

    cudaFuncSetAttribute(ffn1_kernel, cudaFuncAttributeMaxDynamicSharedMemorySize, SMEM_FFN1);
    cudaFuncSetAttribute(ffn2_kernel, cudaFuncAttributeMaxDynamicSharedMemorySize, SMEM_FFN2);

    int write_logits = (out_size >= T * Hd + T * Ed) ? 1 : 0;
    float* out_logits = out + (size_t)T * Hd;

    void* d_xh;
    cudaGetSymbolAddress(&d_xh, g_xh);

    zero_kernel   <<<(T * Hd) / 256, 256>>>(out);
    cvt_h_kernel  <<<(T * Hd / 8) / 256, 256>>>((const float4*)x, (uint4*)d_xh);
    router_kernel <<<T, 256>>>(x, gw, out_logits, write_logits);
    scatter_kernel<<<T / 256, 256>>>();

    dim3 g1(Fd / BN, Ed * 8);
    ffn1_kernel<<<g1, 256, SMEM_FFN1>>>(w1, w3);

    dim3 g2(Hd / BN, Ed * 8);
    ffn2_kernel<<<g2, 256, SMEM_FFN2>>>(w2, out);
}

// round 10
// speedup vs baseline: 1.3805x; 1.3805x over previous
#include <cuda_runtime.h>
#include <cuda_fp16.h>
#include <mma.h>
#include <math.h>
#include <stdint.h>

using namespace nvcuda;

#define T  1024
#define Hd 1024
#define Fd 2048
#define Ed 8

#define BM 128
#define BN 64
#define BK 64                  // halves per stage; 128B data per row
#define KP 72                  // BK + 8 pad halves -> 144B rows
#define RB 144
#define A_BYTES (BM * RB)      // 18432
#define B_BYTES (BN * RB)      // 9216
#define NSTAGE 3
#define OPAD 68

#define F1_A   1024
#define F1_B1  (F1_A  + NSTAGE * A_BYTES)     // 56320
#define F1_B3  (F1_B1 + NSTAGE * B_BYTES)     // 83968
#define SMEM_FFN1 (F1_B3 + NSTAGE * B_BYTES)  // 111616
#define F2_A   1024
#define F2_B   (F2_A + NSTAGE * A_BYTES)      // 56320
#define SMEM_FFN2 (F2_B + NSTAGE * B_BYTES)   // 83968

// ---------------- scratch ----------------
__device__ __half g_interh[(size_t)Ed * T * Fd];         // 32 MB
__device__ __half g_w1h[(size_t)Ed * Fd * Hd];           // 32 MB
__device__ __half g_w3h[(size_t)Ed * Fd * Hd];           // 32 MB
__device__ __half g_w2h[(size_t)Ed * Hd * Fd];           // 32 MB
__device__ __half g_xh[(size_t)T * Hd];                  // 2 MB
__device__ int   g_tok[Ed * T];
__device__ float g_pw[Ed * T];
__device__ int   g_cnt[Ed];
__device__ int   g_sel[T * 2];
__device__ float g_mult[T * 2];

__device__ __forceinline__ uint32_t f2h2(float x, float y) {
    __half2 h = __floats2half2_rn(x, y);
    return *(uint32_t*)&h;
}
__device__ __forceinline__ void cp16(void* s, const void* g) {
    unsigned a = (unsigned)__cvta_generic_to_shared(s);
    asm volatile("cp.async.cg.shared.global [%0], [%1], 16;" :: "r"(a), "l"(g));
}
#define CP_COMMIT() asm volatile("cp.async.commit_group;" ::)
#define CP_WAIT1()  asm volatile("cp.async.wait_group 1;" ::)

// ---------------- kernel 0: fp32 -> fp16 converts (merged) -----------------
// grid (8192, 3): y selects w1/w3/w2. 8 floats per thread.
__global__ __launch_bounds__(256) void cvt_w_kernel(
    const float4* __restrict__ w1, const float4* __restrict__ w3,
    const float4* __restrict__ w2,
    uint4* __restrict__ d1, uint4* __restrict__ d3, uint4* __restrict__ d2)
{
    const float4* src = (blockIdx.y == 0) ? w1 : (blockIdx.y == 1) ? w3 : w2;
    uint4* dst        = (blockIdx.y == 0) ? d1 : (blockIdx.y == 1) ? d3 : d2;
    size_t i = (size_t)blockIdx.x * 256 + threadIdx.x;
    float4 a = src[2 * i];
    float4 b = src[2 * i + 1];
    uint4 o;
    o.x = f2h2(a.x, a.y); o.y = f2h2(a.z, a.w);
    o.z = f2h2(b.x, b.y); o.w = f2h2(b.z, b.w);
    dst[i] = o;
}

__global__ __launch_bounds__(256) void cvt_x_kernel(const float4* __restrict__ src,
                                                    uint4* __restrict__ dst) {
    size_t i = (size_t)blockIdx.x * 256 + threadIdx.x;
    float4 a = src[2 * i];
    float4 b = src[2 * i + 1];
    uint4 o;
    o.x = f2h2(a.x, a.y); o.y = f2h2(a.z, a.w);
    o.z = f2h2(b.x, b.y); o.w = f2h2(b.z, b.w);
    dst[i] = o;
}

// ---------------- kernel 1: router (fp32) + out-zero + cnt-reset -----------
__global__ __launch_bounds__(256) void router_kernel(
    const float* __restrict__ x, const float* __restrict__ gw,
    float* __restrict__ out, float* __restrict__ out_logits, int write_logits)
{
    int t = blockIdx.x, warp = threadIdx.x >> 5, lane = threadIdx.x & 31;

    // zero this token's output row (grid exactly tiles T x Hd)
    float4 z = {0.f, 0.f, 0.f, 0.f};
    ((float4*)(out + (size_t)t * Hd))[threadIdx.x] = z;
    if (t == 0 && threadIdx.x < Ed) g_cnt[threadIdx.x] = 0;

    const float* xr = x + (size_t)t * Hd;
    const float* gr = gw + (size_t)warp * Hd;
    float s = 0.0f;
    for (int h = lane; h < Hd; h += 32) s += xr[h] * gr[h];
    #pragma unroll
    for (int o = 16; o; o >>= 1) s += __shfl_xor_sync(0xFFFFFFFFu, s, o);

    __shared__ float sc[Ed];
    if (lane == 0) sc[warp] = s;
    __syncthreads();
    if (threadIdx.x < Ed && write_logits) out_logits[t * Ed + threadIdx.x] = sc[threadIdx.x];

    if (threadIdx.x == 0) {
        float v[Ed];
        #pragma unroll
        for (int e = 0; e < Ed; e++) v[e] = sc[e];
        int s1 = 0; float m1 = v[0];
        #pragma unroll
        for (int e = 1; e < Ed; e++) if (v[e] > m1) { m1 = v[e]; s1 = e; }
        float Z1 = 0.0f;
        #pragma unroll
        for (int e = 0; e < Ed; e++) {
            float factor = fmaxf(fabsf(v[e]), m1);
            if (!((m1 - v[e]) / factor > 0.02f)) Z1 += expf(v[e] - m1);
        }
        int s2 = -1; float m2 = -INFINITY;
        #pragma unroll
        for (int e = 0; e < Ed; e++) if (e != s1 && v[e] > m2) { m2 = v[e]; s2 = e; }
        float Z2 = 0.0f;
        #pragma unroll
        for (int e = 0; e < Ed; e++) {
            if (e == s1) continue;
            float factor = fmaxf(fabsf(v[e]), m2);
            if (!((m2 - v[e]) / factor > 0.02f)) Z2 += expf(v[e] - m2);
        }
        g_sel [t * 2 + 0] = s1;        g_sel [t * 2 + 1] = s2;
        g_mult[t * 2 + 0] = 1.0f / Z1; g_mult[t * 2 + 1] = 1.0f / Z2;
    }
}

// ---------------- kernel 2: scatter ----------------
__global__ void scatter_kernel() {
    int t = blockIdx.x * 256 + threadIdx.x;
    if (t >= T) return;
    #pragma unroll
    for (int k = 0; k < 2; k++) {
        int e = g_sel[t * 2 + k];
        int p = atomicAdd(&g_cnt[e], 1);
        g_tok[e * T + p] = t;
        g_pw [e * T + p] = g_mult[t * 2 + k];
    }
}

// ---------------- kernel 3: ffn1 (fp16 wmma, BK=64) -------------------------
// grid (Fd/BN=32, Ed*8=64), 256 threads (8 warps, 4m x 2n), warp 32x32 dual
__global__ __launch_bounds__(256, 2) void ffn1_kernel()
{
    extern __shared__ char sm[];
    int e   = blockIdx.y >> 3;
    int mt  = blockIdx.y & 7;
    int cnt = g_cnt[e];
    int m0  = mt * BM;
    if (m0 >= cnt) return;
    int f0  = blockIdx.x * BN;

    int* toks = (int*)sm;
    int tid = threadIdx.x;
    if (tid < BM) {
        int i = m0 + tid;
        toks[tid] = (i < cnt) ? g_tok[e * T + i] : g_tok[e * T];
    }
    __syncthreads();

    int arow = tid >> 3;                 // 0..31
    int col8 = (tid & 7) * 8;            // half offset of 16B chunk
    uint32_t so = (uint32_t)arow * RB + (tid & 7) * 16;

    const __half* ap0 = g_xh + (size_t)toks[arow     ] * Hd + col8;
    const __half* ap1 = g_xh + (size_t)toks[arow + 32] * Hd + col8;
    const __half* ap2 = g_xh + (size_t)toks[arow + 64] * Hd + col8;
    const __half* ap3 = g_xh + (size_t)toks[arow + 96] * Hd + col8;
    const __half* b1p = g_w1h + (size_t)e * Fd * Hd + (size_t)(f0 + arow) * Hd + col8;
    const __half* b3p = g_w3h + (size_t)e * Fd * Hd + (size_t)(f0 + arow) * Hd + col8;
    const size_t BROW = (size_t)32 * Hd;

    char* smA  = sm + F1_A;
    char* smB1 = sm + F1_B1;
    char* smB3 = sm + F1_B3;

    const int NS = Hd / BK;   // 16
    #pragma unroll
    for (int s = 0; s < NSTAGE - 1; s++) {
        int k0 = s * BK;
        char* A = smA + s * A_BYTES;
        cp16(A + so,           ap0 + k0);
        cp16(A + so + 32 * RB, ap1 + k0);
        cp16(A + so + 64 * RB, ap2 + k0);
        cp16(A + so + 96 * RB, ap3 + k0);
        cp16(smB1 + s * B_BYTES + so,           b1p + k0);
        cp16(smB1 + s * B_BYTES + so + 32 * RB, b1p + BROW + k0);
        cp16(smB3 + s * B_BYTES + so,           b3p + k0);
        cp16(smB3 + s * B_BYTES + so + 32 * RB, b3p + BROW + k0);
        CP_COMMIT();
    }

    wmma::fragment<wmma::matrix_a, 16,16,16, __half, wmma::row_major> fa[2];
    wmma::fragment<wmma::matrix_b, 16,16,16, __half, wmma::col_major> fb1[2], fb3[2];
    wmma::fragment<wmma::accumulator, 16,16,16, float> acc1[2][2], acc3[2][2];
    #pragma unroll
    for (int i = 0; i < 2; i++)
        #pragma unroll
        for (int j = 0; j < 2; j++) { wmma::fill_fragment(acc1[i][j], 0.f); wmma::fill_fragment(acc3[i][j], 0.f); }

    int wid = tid >> 5;
    int wm  = wid >> 1;     // 0..3
    int wn  = wid & 1;      // 0..1

    int cur = 0;
    for (int s = 0; s < NS; s++) {
        CP_WAIT1();
        __syncthreads();
        if (s + 2 < NS) {
            int b2 = (s + 2) % NSTAGE;
            int k0 = (s + 2) * BK;
            char* A = smA + b2 * A_BYTES;
            cp16(A + so,           ap0 + k0);
            cp16(A + so + 32 * RB, ap1 + k0);
            cp16(A + so + 64 * RB, ap2 + k0);
            cp16(A + so + 96 * RB, ap3 + k0);
            cp16(smB1 + b2 * B_BYTES + so,           b1p + k0);
            cp16(smB1 + b2 * B_BYTES + so + 32 * RB, b1p + BROW + k0);
            cp16(smB3 + b2 * B_BYTES + so,           b3p + k0);
            cp16(smB3 + b2 * B_BYTES + so + 32 * RB, b3p + BROW + k0);
        }
        CP_COMMIT();

        const __half* Ab  = (const __half*)(smA  + cur * A_BYTES);
        const __half* B1b = (const __half*)(smB1 + cur * B_BYTES);
        const __half* B3b = (const __half*)(smB3 + cur * B_BYTES);
        #pragma unroll
        for (int ks = 0; ks < BK; ks += 16) {
            wmma::load_matrix_sync(fa[0],  Ab  + (wm*32     ) * KP + ks, KP);
            wmma::load_matrix_sync(fa[1],  Ab  + (wm*32 + 16) * KP + ks, KP);
            wmma::load_matrix_sync(fb1[0], B1b + (wn*32     ) * KP + ks, KP);
            wmma::load_matrix_sync(fb1[1], B1b + (wn*32 + 16) * KP + ks, KP);
            wmma::load_matrix_sync(fb3[0], B3b + (wn*32     ) * KP + ks, KP);
            wmma::load_matrix_sync(fb3[1], B3b + (wn*32 + 16) * KP + ks, KP);
            #pragma unroll
            for (int i = 0; i < 2; i++)
                #pragma unroll
                for (int j = 0; j < 2; j++) {
                    wmma::mma_sync(acc1[i][j], fa[i], fb1[j], acc1[i][j]);
                    wmma::mma_sync(acc3[i][j], fa[i], fb3[j], acc3[i][j]);
                }
        }
        cur = (cur + 1 == NSTAGE) ? 0 : cur + 1;
    }

    // epilogue: silu(h1)*h3 -> pool (f32) -> half2 stores to g_interh
    __syncthreads();
    float* pool = (float*)(sm + F1_A);
    #pragma unroll
    for (int i = 0; i < 2; i++)
        #pragma unroll
        for (int j = 0; j < 2; j++) {
            #pragma unroll
            for (int el = 0; el < acc1[i][j].num_elements; el++) {
                float h1 = acc1[i][j].x[el], h3 = acc3[i][j].x[el];
                acc1[i][j].x[el] = h1 / (1.0f + expf(-h1)) * h3;
            }
            wmma::store_matrix_sync(
                pool + (size_t)(wm*32 + i*16) * OPAD + wn*32 + j*16,
                acc1[i][j], OPAD, wmma::mem_row_major);
        }
    __syncthreads();

    for (int idx = tid; idx < BM * BN / 2; idx += 256) {
        int r  = idx >> 5;
        int c2 = idx & 31;
        uint32_t h = f2h2(pool[r * OPAD + 2*c2], pool[r * OPAD + 2*c2 + 1]);
        *(uint32_t*)&g_interh[((size_t)e * T + m0 + r) * Fd + f0 + 2*c2] = h;
    }
}

// ---------------- kernel 4: ffn2 (fp16 wmma, BK=64) -------------------------
// grid (Hd/BN=16, Ed*8=64), 256 threads, warp 32x32
__global__ __launch_bounds__(256, 2) void ffn2_kernel(float* __restrict__ out)
{
    extern __shared__ char sm[];
    int e   = blockIdx.y >> 3;
    int mt  = blockIdx.y & 7;
    int cnt = g_cnt[e];
    int m0  = mt * BM;
    if (m0 >= cnt) return;
    int h0  = blockIdx.x * BN;

    int*   toks = (int*)sm;
    float* pws  = (float*)(sm + 512);
    int tid = threadIdx.x;
    if (tid < BM) {
        int i = m0 + tid;
        toks[tid] = (i < cnt) ? g_tok[e * T + i] : 0;
        pws [tid] = (i < cnt) ? g_pw [e * T + i] : 0.0f;
    }
    __syncthreads();

    int arow = tid >> 3;
    int col8 = (tid & 7) * 8;
    uint32_t so = (uint32_t)arow * RB + (tid & 7) * 16;

    const __half* ag = &g_interh[((size_t)e * T + m0 + arow) * Fd + col8];
    const __half* bg = g_w2h + ((size_t)e * Hd + h0 + arow) * Fd + col8;
    const size_t AROW = (size_t)32 * Fd;

    char* smA = sm + F2_A;
    char* smB = sm + F2_B;

    const int NS = Fd / BK;   // 32
    #pragma unroll
    for (int s = 0; s < NSTAGE - 1; s++) {
        int k0 = s * BK;
        char* A = smA + s * A_BYTES;
        cp16(A + so,           ag + k0);
        cp16(A + so + 32 * RB, ag + AROW + k0);
        cp16(A + so + 64 * RB, ag + 2 * AROW + k0);
        cp16(A + so + 96 * RB, ag + 3 * AROW + k0);
        cp16(smB + s * B_BYTES + so,           bg + k0);
        cp16(smB + s * B_BYTES + so + 32 * RB, bg + AROW + k0);
        CP_COMMIT();
    }

    wmma::fragment<wmma::matrix_a, 16,16,16, __half, wmma::row_major> fa[2];
    wmma::fragment<wmma::matrix_b, 16,16,16, __half, wmma::col_major> fb[2];
    wmma::fragment<wmma::accumulator, 16,16,16, float> acc[2][2];
    #pragma unroll
    for (int i = 0; i < 2; i++)
        #pragma unroll
        for (int j = 0; j < 2; j++) wmma::fill_fragment(acc[i][j], 0.f);

    int wid = tid >> 5;
    int wm  = wid >> 1;
    int wn  = wid & 1;

    int cur = 0;
    for (int s = 0; s < NS; s++) {
        CP_WAIT1();
        __syncthreads();
        if (s + 2 < NS) {
            int b2 = (s + 2) % NSTAGE;
            int k0 = (s + 2) * BK;
            char* A = smA + b2 * A_BYTES;
            cp16(A + so,           ag + k0);
            cp16(A + so + 32 * RB, ag + AROW + k0);
            cp16(A + so + 64 * RB, ag + 2 * AROW + k0);
            cp16(A + so + 96 * RB, ag + 3 * AROW + k0);
            cp16(smB + b2 * B_BYTES + so,           bg + k0);
            cp16(smB + b2 * B_BYTES + so + 32 * RB, bg + AROW + k0);
        }
        CP_COMMIT();

        const __half* Ab = (const __half*)(smA + cur * A_BYTES);
        const __half* Bb = (const __half*)(smB + cur * B_BYTES);
        #pragma unroll
        for (int ks = 0; ks < BK; ks += 16) {
            wmma::load_matrix_sync(fa[0], Ab + (wm*32     ) * KP + ks, KP);
            wmma::load_matrix_sync(fa[1], Ab + (wm*32 + 16) * KP + ks, KP);
            wmma::load_matrix_sync(fb[0], Bb + (wn*32     ) * KP + ks, KP);
            wmma::load_matrix_sync(fb[1], Bb + (wn*32 + 16) * KP + ks, KP);
            #pragma unroll
            for (int i = 0; i < 2; i++)
                #pragma unroll
                for (int j = 0; j < 2; j++)
                    wmma::mma_sync(acc[i][j], fa[i], fb[j], acc[i][j]);
        }
        cur = (cur + 1 == NSTAGE) ? 0 : cur + 1;
    }

    __syncthreads();
    float* pool = (float*)(sm + F2_A);
    #pragma unroll
    for (int i = 0; i < 2; i++)
        #pragma unroll
        for (int j = 0; j < 2; j++)
            wmma::store_matrix_sync(
                pool + (size_t)(wm*32 + i*16) * OPAD + wn*32 + j*16,
                acc[i][j], OPAD, wmma::mem_row_major);
    __syncthreads();

    for (int idx = tid; idx < BM * BN; idx += 256) {
        int r = idx >> 6;
        int c = idx & 63;
        if (m0 + r < cnt)
            atomicAdd(&out[(size_t)toks[r] * Hd + h0 + c], pws[r] * pool[r * OPAD + c]);
    }
}

// ---------------- launch ----------------
extern "C" void kernel_launch(void* const* d_in, const int* in_sizes, int n_in,
                              void* d_out, int out_size)
{
    const float* x  = (const float*)d_in[0];
    const float* gw = (const float*)d_in[1];
    const float* w1 = (const float*)d_in[2];
    const float* w2 = (const float*)d_in[3];
    const float* w3 = (const float*)d_in[4];
    float* out = (float*)d_out;

    cudaFuncSetAttribute(ffn1_kernel, cudaFuncAttributeMaxDynamicSharedMemorySize, SMEM_FFN1);
    cudaFuncSetAttribute(ffn2_kernel, cudaFuncAttributeMaxDynamicSharedMemorySize, SMEM_FFN2);

    int write_logits = (out_size >= T * Hd + T * Ed) ? 1 : 0;
    float* out_logits = out + (size_t)T * Hd;

    void *d_w1h, *d_w3h, *d_w2h, *d_xh;
    cudaGetSymbolAddress(&d_w1h, g_w1h);
    cudaGetSymbolAddress(&d_w3h, g_w3h);
    cudaGetSymbolAddress(&d_w2h, g_w2h);
    cudaGetSymbolAddress(&d_xh,  g_xh);

    // merged converts (memory-bound)
    dim3 gc((unsigned)((size_t)Ed * Fd * Hd / 8 / 256), 3);
    cvt_w_kernel<<<gc, 256>>>((const float4*)w1, (const float4*)w3, (const float4*)w2,
                              (uint4*)d_w1h, (uint4*)d_w3h, (uint4*)d_w2h);
    cvt_x_kernel<<<(T * Hd / 8) / 256, 256>>>((const float4*)x, (uint4*)d_xh);

    router_kernel <<<T, 256>>>(x, gw, out, out_logits, write_logits);
    scatter_kernel<<<T / 256, 256>>>();

    dim3 g1(Fd / BN, Ed * 8);
    ffn1_kernel<<<g1, 256, SMEM_FFN1>>>();

    dim3 g2(Hd / BN, Ed * 8);
    ffn2_kernel<<<g2, 256, SMEM_FFN2>>>(out);
}

// round 11
// speedup vs baseline: 1.4150x; 1.0250x over previous
#include <cuda_runtime.h>
#include <cuda_fp16.h>
#include <mma.h>
#include <math.h>
#include <stdint.h>

using namespace nvcuda;

#define T  1024
#define Hd 1024
#define Fd 2048
#define Ed 8

#define BM 128
#define BN 64
#define BK 64                  // halves per stage; 128B data per row
#define KP 72                  // BK + 8 pad halves -> 144B rows
#define RB 144
#define A_BYTES (BM * RB)      // 18432
#define B_BYTES (BN * RB)      // 9216
#define NSTAGE 3
#define OPAD 68

#define F1_A   1024
#define F1_B1  (F1_A  + NSTAGE * A_BYTES)
#define F1_B3  (F1_B1 + NSTAGE * B_BYTES)
#define SMEM_FFN1 (F1_B3 + NSTAGE * B_BYTES)  // 111616
#define F2_A   1024
#define F2_B   (F2_A + NSTAGE * A_BYTES)
#define SMEM_FFN2 (F2_B + NSTAGE * B_BYTES)   // 83968

// ---------------- scratch ----------------
__device__ __half g_interh[(size_t)Ed * T * Fd];
__device__ __half g_w1h[(size_t)Ed * Fd * Hd];
__device__ __half g_w3h[(size_t)Ed * Fd * Hd];
__device__ __half g_w2h[(size_t)Ed * Hd * Fd];
__device__ __half g_xh[(size_t)T * Hd];
__device__ int   g_tok[Ed * T];
__device__ float g_pw[Ed * T];
__device__ int   g_cnt[Ed];

#define WSEG 8192   // blocks per weight segment
#define XSEG 512    // blocks for x segment

__device__ __forceinline__ uint32_t f2h2(float x, float y) {
    __half2 h = __floats2half2_rn(x, y);
    return *(uint32_t*)&h;
}
__device__ __forceinline__ void cp16(void* s, const void* g) {
    unsigned a = (unsigned)__cvta_generic_to_shared(s);
    asm volatile("cp.async.cg.shared.global [%0], [%1], 16;" :: "r"(a), "l"(g));
}
#define CP_COMMIT() asm volatile("cp.async.commit_group;" ::)
#define CP_WAIT1()  asm volatile("cp.async.wait_group 1;" ::)

// ---------------- kernel 0: all fp32->fp16 converts + counter reset --------
// flat grid 3*WSEG + XSEG blocks; 8 floats/thread
__global__ __launch_bounds__(256) void cvt_all_kernel(
    const float4* __restrict__ w1, const float4* __restrict__ w3,
    const float4* __restrict__ w2, const float4* __restrict__ x,
    uint4* __restrict__ d1, uint4* __restrict__ d3,
    uint4* __restrict__ d2, uint4* __restrict__ dx)
{
    int b = blockIdx.x;
    if (b == 0 && threadIdx.x < Ed) g_cnt[threadIdx.x] = 0;

    const float4* src;
    uint4* dst;
    size_t base;
    if (b < WSEG)          { src = w1; dst = d1; base = (size_t)b * 256; }
    else if (b < 2*WSEG)   { src = w3; dst = d3; base = (size_t)(b - WSEG) * 256; }
    else if (b < 3*WSEG)   { src = w2; dst = d2; base = (size_t)(b - 2*WSEG) * 256; }
    else                   { src = x;  dst = dx; base = (size_t)(b - 3*WSEG) * 256; }

    size_t i = base + threadIdx.x;
    float4 a = src[2 * i];
    float4 c = src[2 * i + 1];
    uint4 o;
    o.x = f2h2(a.x, a.y); o.y = f2h2(a.z, a.w);
    o.z = f2h2(c.x, c.y); o.w = f2h2(c.z, c.w);
    dst[i] = o;
}

// ---------------- kernel 1: router + out-zero + inline scatter -------------
__global__ __launch_bounds__(256) void router_kernel(
    const float* __restrict__ x, const float* __restrict__ gw,
    float* __restrict__ out, float* __restrict__ out_logits, int write_logits)
{
    int t = blockIdx.x, warp = threadIdx.x >> 5, lane = threadIdx.x & 31;

    // zero this token's output row (grid exactly tiles T x Hd as float4)
    float4 z = {0.f, 0.f, 0.f, 0.f};
    ((float4*)(out + (size_t)t * Hd))[threadIdx.x] = z;

    const float* xr = x + (size_t)t * Hd;
    const float* gr = gw + (size_t)warp * Hd;
    float s = 0.0f;
    for (int h = lane; h < Hd; h += 32) s += xr[h] * gr[h];
    #pragma unroll
    for (int o = 16; o; o >>= 1) s += __shfl_xor_sync(0xFFFFFFFFu, s, o);

    __shared__ float sc[Ed];
    if (lane == 0) sc[warp] = s;
    __syncthreads();
    if (threadIdx.x < Ed && write_logits) out_logits[t * Ed + threadIdx.x] = sc[threadIdx.x];

    if (threadIdx.x == 0) {
        float v[Ed];
        #pragma unroll
        for (int e = 0; e < Ed; e++) v[e] = sc[e];
        int s1 = 0; float m1 = v[0];
        #pragma unroll
        for (int e = 1; e < Ed; e++) if (v[e] > m1) { m1 = v[e]; s1 = e; }
        float Z1 = 0.0f;
        #pragma unroll
        for (int e = 0; e < Ed; e++) {
            float factor = fmaxf(fabsf(v[e]), m1);
            if (!((m1 - v[e]) / factor > 0.02f)) Z1 += expf(v[e] - m1);
        }
        int s2 = -1; float m2 = -INFINITY;
        #pragma unroll
        for (int e = 0; e < Ed; e++) if (e != s1 && v[e] > m2) { m2 = v[e]; s2 = e; }
        float Z2 = 0.0f;
        #pragma unroll
        for (int e = 0; e < Ed; e++) {
            if (e == s1) continue;
            float factor = fmaxf(fabsf(v[e]), m2);
            if (!((m2 - v[e]) / factor > 0.02f)) Z2 += expf(v[e] - m2);
        }
        // inline scatter
        int p1 = atomicAdd(&g_cnt[s1], 1);
        g_tok[s1 * T + p1] = t;  g_pw[s1 * T + p1] = 1.0f / Z1;
        int p2 = atomicAdd(&g_cnt[s2], 1);
        g_tok[s2 * T + p2] = t;  g_pw[s2 * T + p2] = 1.0f / Z2;
    }
}

// ---------------- kernel 2: ffn1 (fp16 wmma, BK=64) -------------------------
// grid (Fd/BN=32, Ed*8=64), 256 threads (8 warps, 4m x 2n), warp 32x32 dual
__global__ __launch_bounds__(256, 2) void ffn1_kernel()
{
    extern __shared__ char sm[];
    int e   = blockIdx.y >> 3;
    int mt  = blockIdx.y & 7;
    int cnt = g_cnt[e];
    int m0  = mt * BM;
    if (m0 >= cnt) return;
    int f0  = blockIdx.x * BN;

    int* toks = (int*)sm;
    int tid = threadIdx.x;
    if (tid < BM) {
        int i = m0 + tid;
        toks[tid] = (i < cnt) ? g_tok[e * T + i] : g_tok[e * T];
    }
    __syncthreads();

    int arow = tid >> 3;
    int col8 = (tid & 7) * 8;
    uint32_t so = (uint32_t)arow * RB + (tid & 7) * 16;

    const __half* ap0 = g_xh + (size_t)toks[arow     ] * Hd + col8;
    const __half* ap1 = g_xh + (size_t)toks[arow + 32] * Hd + col8;
    const __half* ap2 = g_xh + (size_t)toks[arow + 64] * Hd + col8;
    const __half* ap3 = g_xh + (size_t)toks[arow + 96] * Hd + col8;
    const __half* b1p = g_w1h + (size_t)e * Fd * Hd + (size_t)(f0 + arow) * Hd + col8;
    const __half* b3p = g_w3h + (size_t)e * Fd * Hd + (size_t)(f0 + arow) * Hd + col8;
    const size_t BROW = (size_t)32 * Hd;

    char* smA  = sm + F1_A;
    char* smB1 = sm + F1_B1;
    char* smB3 = sm + F1_B3;

    const int NS = Hd / BK;   // 16
    #pragma unroll
    for (int s = 0; s < NSTAGE - 1; s++) {
        int k0 = s * BK;
        char* A = smA + s * A_BYTES;
        cp16(A + so,           ap0 + k0);
        cp16(A + so + 32 * RB, ap1 + k0);
        cp16(A + so + 64 * RB, ap2 + k0);
        cp16(A + so + 96 * RB, ap3 + k0);
        cp16(smB1 + s * B_BYTES + so,           b1p + k0);
        cp16(smB1 + s * B_BYTES + so + 32 * RB, b1p + BROW + k0);
        cp16(smB3 + s * B_BYTES + so,           b3p + k0);
        cp16(smB3 + s * B_BYTES + so + 32 * RB, b3p + BROW + k0);
        CP_COMMIT();
    }

    wmma::fragment<wmma::matrix_a, 16,16,16, __half, wmma::row_major> fa[2];
    wmma::fragment<wmma::matrix_b, 16,16,16, __half, wmma::col_major> fb1[2], fb3[2];
    wmma::fragment<wmma::accumulator, 16,16,16, float> acc1[2][2], acc3[2][2];
    #pragma unroll
    for (int i = 0; i < 2; i++)
        #pragma unroll
        for (int j = 0; j < 2; j++) { wmma::fill_fragment(acc1[i][j], 0.f); wmma::fill_fragment(acc3[i][j], 0.f); }

    int wid = tid >> 5;
    int wm  = wid >> 1;
    int wn  = wid & 1;

    int cur = 0;
    for (int s = 0; s < NS; s++) {
        CP_WAIT1();
        __syncthreads();
        if (s + 2 < NS) {
            int b2 = (s + 2) % NSTAGE;
            int k0 = (s + 2) * BK;
            char* A = smA + b2 * A_BYTES;
            cp16(A + so,           ap0 + k0);
            cp16(A + so + 32 * RB, ap1 + k0);
            cp16(A + so + 64 * RB, ap2 + k0);
            cp16(A + so + 96 * RB, ap3 + k0);
            cp16(smB1 + b2 * B_BYTES + so,           b1p + k0);
            cp16(smB1 + b2 * B_BYTES + so + 32 * RB, b1p + BROW + k0);
            cp16(smB3 + b2 * B_BYTES + so,           b3p + k0);
            cp16(smB3 + b2 * B_BYTES + so + 32 * RB, b3p + BROW + k0);
        }
        CP_COMMIT();

        const __half* Ab  = (const __half*)(smA  + cur * A_BYTES);
        const __half* B1b = (const __half*)(smB1 + cur * B_BYTES);
        const __half* B3b = (const __half*)(smB3 + cur * B_BYTES);
        #pragma unroll
        for (int ks = 0; ks < BK; ks += 16) {
            wmma::load_matrix_sync(fa[0],  Ab  + (wm*32     ) * KP + ks, KP);
            wmma::load_matrix_sync(fa[1],  Ab  + (wm*32 + 16) * KP + ks, KP);
            wmma::load_matrix_sync(fb1[0], B1b + (wn*32     ) * KP + ks, KP);
            wmma::load_matrix_sync(fb1[1], B1b + (wn*32 + 16) * KP + ks, KP);
            wmma::load_matrix_sync(fb3[0], B3b + (wn*32     ) * KP + ks, KP);
            wmma::load_matrix_sync(fb3[1], B3b + (wn*32 + 16) * KP + ks, KP);
            #pragma unroll
            for (int i = 0; i < 2; i++)
                #pragma unroll
                for (int j = 0; j < 2; j++) {
                    wmma::mma_sync(acc1[i][j], fa[i], fb1[j], acc1[i][j]);
                    wmma::mma_sync(acc3[i][j], fa[i], fb3[j], acc3[i][j]);
                }
        }
        cur = (cur + 1 == NSTAGE) ? 0 : cur + 1;
    }

    __syncthreads();
    float* pool = (float*)(sm + F1_A);
    #pragma unroll
    for (int i = 0; i < 2; i++)
        #pragma unroll
        for (int j = 0; j < 2; j++) {
            #pragma unroll
            for (int el = 0; el < acc1[i][j].num_elements; el++) {
                float h1 = acc1[i][j].x[el], h3 = acc3[i][j].x[el];
                acc1[i][j].x[el] = h1 / (1.0f + expf(-h1)) * h3;
            }
            wmma::store_matrix_sync(
                pool + (size_t)(wm*32 + i*16) * OPAD + wn*32 + j*16,
                acc1[i][j], OPAD, wmma::mem_row_major);
        }
    __syncthreads();

    for (int idx = tid; idx < BM * BN / 2; idx += 256) {
        int r  = idx >> 5;
        int c2 = idx & 31;
        uint32_t h = f2h2(pool[r * OPAD + 2*c2], pool[r * OPAD + 2*c2 + 1]);
        *(uint32_t*)&g_interh[((size_t)e * T + m0 + r) * Fd + f0 + 2*c2] = h;
    }
}

// ---------------- kernel 3: ffn2 (fp16 wmma, BK=64) -------------------------
// grid (Hd/BN=16, Ed*8=64), 256 threads, warp 32x32
__global__ __launch_bounds__(256, 2) void ffn2_kernel(float* __restrict__ out)
{
    extern __shared__ char sm[];
    int e   = blockIdx.y >> 3;
    int mt  = blockIdx.y & 7;
    int cnt = g_cnt[e];
    int m0  = mt * BM;
    if (m0 >= cnt) return;
    int h0  = blockIdx.x * BN;

    int*   toks = (int*)sm;
    float* pws  = (float*)(sm + 512);
    int tid = threadIdx.x;
    if (tid < BM) {
        int i = m0 + tid;
        toks[tid] = (i < cnt) ? g_tok[e * T + i] : 0;
        pws [tid] = (i < cnt) ? g_pw [e * T + i] : 0.0f;
    }
    __syncthreads();

    int arow = tid >> 3;
    int col8 = (tid & 7) * 8;
    uint32_t so = (uint32_t)arow * RB + (tid & 7) * 16;

    const __half* ag = &g_interh[((size_t)e * T + m0 + arow) * Fd + col8];
    const __half* bg = g_w2h + ((size_t)e * Hd + h0 + arow) * Fd + col8;
    const size_t AROW = (size_t)32 * Fd;

    char* smA = sm + F2_A;
    char* smB = sm + F2_B;

    const int NS = Fd / BK;   // 32
    #pragma unroll
    for (int s = 0; s < NSTAGE - 1; s++) {
        int k0 = s * BK;
        char* A = smA + s * A_BYTES;
        cp16(A + so,           ag + k0);
        cp16(A + so + 32 * RB, ag + AROW + k0);
        cp16(A + so + 64 * RB, ag + 2 * AROW + k0);
        cp16(A + so + 96 * RB, ag + 3 * AROW + k0);
        cp16(smB + s * B_BYTES + so,           bg + k0);
        cp16(smB + s * B_BYTES + so + 32 * RB, bg + AROW + k0);
        CP_COMMIT();
    }

    wmma::fragment<wmma::matrix_a, 16,16,16, __half, wmma::row_major> fa[2];
    wmma::fragment<wmma::matrix_b, 16,16,16, __half, wmma::col_major> fb[2];
    wmma::fragment<wmma::accumulator, 16,16,16, float> acc[2][2];
    #pragma unroll
    for (int i = 0; i < 2; i++)
        #pragma unroll
        for (int j = 0; j < 2; j++) wmma::fill_fragment(acc[i][j], 0.f);

    int wid = tid >> 5;
    int wm  = wid >> 1;
    int wn  = wid & 1;

    int cur = 0;
    for (int s = 0; s < NS; s++) {
        CP_WAIT1();
        __syncthreads();
        if (s + 2 < NS) {
            int b2 = (s + 2) % NSTAGE;
            int k0 = (s + 2) * BK;
            char* A = smA + b2 * A_BYTES;
            cp16(A + so,           ag + k0);
            cp16(A + so + 32 * RB, ag + AROW + k0);
            cp16(A + so + 64 * RB, ag + 2 * AROW + k0);
            cp16(A + so + 96 * RB, ag + 3 * AROW + k0);
            cp16(smB + b2 * B_BYTES + so,           bg + k0);
            cp16(smB + b2 * B_BYTES + so + 32 * RB, bg + AROW + k0);
        }
        CP_COMMIT();

        const __half* Ab = (const __half*)(smA + cur * A_BYTES);
        const __half* Bb = (const __half*)(smB + cur * B_BYTES);
        #pragma unroll
        for (int ks = 0; ks < BK; ks += 16) {
            wmma::load_matrix_sync(fa[0], Ab + (wm*32     ) * KP + ks, KP);
            wmma::load_matrix_sync(fa[1], Ab + (wm*32 + 16) * KP + ks, KP);
            wmma::load_matrix_sync(fb[0], Bb + (wn*32     ) * KP + ks, KP);
            wmma::load_matrix_sync(fb[1], Bb + (wn*32 + 16) * KP + ks, KP);
            #pragma unroll
            for (int i = 0; i < 2; i++)
                #pragma unroll
                for (int j = 0; j < 2; j++)
                    wmma::mma_sync(acc[i][j], fa[i], fb[j], acc[i][j]);
        }
        cur = (cur + 1 == NSTAGE) ? 0 : cur + 1;
    }

    __syncthreads();
    float* pool = (float*)(sm + F2_A);
    #pragma unroll
    for (int i = 0; i < 2; i++)
        #pragma unroll
        for (int j = 0; j < 2; j++)
            wmma::store_matrix_sync(
                pool + (size_t)(wm*32 + i*16) * OPAD + wn*32 + j*16,
                acc[i][j], OPAD, wmma::mem_row_major);
    __syncthreads();

    for (int idx = tid; idx < BM * BN; idx += 256) {
        int r = idx >> 6;
        int c = idx & 63;
        if (m0 + r < cnt)
            atomicAdd(&out[(size_t)toks[r] * Hd + h0 + c], pws[r] * pool[r * OPAD + c]);
    }
}

// ---------------- launch ----------------
extern "C" void kernel_launch(void* const* d_in, const int* in_sizes, int n_in,
                              void* d_out, int out_size)
{
    const float* x  = (const float*)d_in[0];
    const float* gw = (const float*)d_in[1];
    const float* w1 = (const float*)d_in[2];
    const float* w2 = (const float*)d_in[3];
    const float* w3 = (const float*)d_in[4];
    float* out = (float*)d_out;

    cudaFuncSetAttribute(ffn1_kernel, cudaFuncAttributeMaxDynamicSharedMemorySize, SMEM_FFN1);
    cudaFuncSetAttribute(ffn2_kernel, cudaFuncAttributeMaxDynamicSharedMemorySize, SMEM_FFN2);

    int write_logits = (out_size >= T * Hd + T * Ed) ? 1 : 0;
    float* out_logits = out + (size_t)T * Hd;

    void *d_w1h, *d_w3h, *d_w2h, *d_xh;
    cudaGetSymbolAddress(&d_w1h, g_w1h);
    cudaGetSymbolAddress(&d_w3h, g_w3h);
    cudaGetSymbolAddress(&d_w2h, g_w2h);
    cudaGetSymbolAddress(&d_xh,  g_xh);

    cvt_all_kernel<<<3 * WSEG + XSEG, 256>>>(
        (const float4*)w1, (const float4*)w3, (const float4*)w2, (const float4*)x,
        (uint4*)d_w1h, (uint4*)d_w3h, (uint4*)d_w2h, (uint4*)d_xh);

    router_kernel<<<T, 256>>>(x, gw, out, out_logits, write_logits);

    dim3 g1(Fd / BN, Ed * 8);
    ffn1_kernel<<<g1, 256, SMEM_FFN1>>>();

    dim3 g2(Hd / BN, Ed * 8);
    ffn2_kernel<<<g2, 256, SMEM_FFN2>>>(out);
}

// round 12
// speedup vs baseline: 1.4512x; 1.0256x over previous
#include <cuda_runtime.h>
#include <cuda_fp16.h>
#include <mma.h>
#include <math.h>
#include <stdint.h>

using namespace nvcuda;

#define T  1024
#define Hd 1024
#define Fd 2048
#define Ed 8

#define BM 128
#define BN 64
#define BK 64                  // halves per stage; 128B data per row
#define KP 72                  // BK + 8 pad halves -> 144B rows
#define RB 144
#define A_BYTES (BM * RB)      // 18432
#define B_BYTES (BN * RB)      // 9216
#define NSTAGE 3
#define OPAD 68

#define F1_A   1024
#define F1_B1  (F1_A  + NSTAGE * A_BYTES)
#define F1_B3  (F1_B1 + NSTAGE * B_BYTES)
#define SMEM_FFN1 (F1_B3 + NSTAGE * B_BYTES)  // 111616
#define F2_A   1024
#define F2_B   (F2_A + NSTAGE * A_BYTES)
#define SMEM_FFN2 (F2_B + NSTAGE * B_BYTES)   // 83968

// ---------------- scratch ----------------
__device__ __half g_interh[(size_t)Ed * T * Fd];
__device__ __half g_w1h[(size_t)Ed * Fd * Hd];
__device__ __half g_w3h[(size_t)Ed * Fd * Hd];
__device__ __half g_w2h[(size_t)Ed * Hd * Fd];
__device__ __half g_xh[(size_t)T * Hd];
__device__ int   g_tok[Ed * T];
__device__ float g_pw[Ed * T];
__device__ int   g_cnt[Ed];

#define WSEG 8192   // blocks per weight segment
#define XSEG 512    // blocks for x segment

__device__ __forceinline__ uint32_t f2h2(float x, float y) {
    __half2 h = __floats2half2_rn(x, y);
    return *(uint32_t*)&h;
}
__device__ __forceinline__ void cp16(void* s, const void* g) {
    unsigned a = (unsigned)__cvta_generic_to_shared(s);
    asm volatile("cp.async.cg.shared.global [%0], [%1], 16;" :: "r"(a), "l"(g));
}
#define CP_COMMIT() asm volatile("cp.async.commit_group;" ::)
#define CP_WAIT1()  asm volatile("cp.async.wait_group 1;" ::)

// ---------------- kernel 0a: w1/w3/x converts + counter reset --------------
__global__ __launch_bounds__(256) void cvt_w13x_kernel(
    const float4* __restrict__ w1, const float4* __restrict__ w3,
    const float4* __restrict__ x,
    uint4* __restrict__ d1, uint4* __restrict__ d3, uint4* __restrict__ dx)
{
    int b = blockIdx.x;
    if (b == 0 && threadIdx.x < Ed) g_cnt[threadIdx.x] = 0;

    const float4* src;
    uint4* dst;
    size_t base;
    if (b < WSEG)        { src = w1; dst = d1; base = (size_t)b * 256; }
    else if (b < 2*WSEG) { src = w3; dst = d3; base = (size_t)(b - WSEG) * 256; }
    else                 { src = x;  dst = dx; base = (size_t)(b - 2*WSEG) * 256; }

    size_t i = base + threadIdx.x;
    float4 a = src[2 * i];
    float4 c = src[2 * i + 1];
    uint4 o;
    o.x = f2h2(a.x, a.y); o.y = f2h2(a.z, a.w);
    o.z = f2h2(c.x, c.y); o.w = f2h2(c.z, c.w);
    dst[i] = o;
}

// ---------------- kernel 0b: w2 convert (overlapped with ffn1) --------------
__global__ __launch_bounds__(256) void cvt_w2_kernel(
    const float4* __restrict__ w2, uint4* __restrict__ d2)
{
    size_t i = (size_t)blockIdx.x * 256 + threadIdx.x;
    float4 a = w2[2 * i];
    float4 c = w2[2 * i + 1];
    uint4 o;
    o.x = f2h2(a.x, a.y); o.y = f2h2(a.z, a.w);
    o.z = f2h2(c.x, c.y); o.w = f2h2(c.z, c.w);
    d2[i] = o;
}

// ---------------- kernel 1: router + out-zero + inline scatter -------------
__global__ __launch_bounds__(256) void router_kernel(
    const float* __restrict__ x, const float* __restrict__ gw,
    float* __restrict__ out, float* __restrict__ out_logits, int write_logits)
{
    int t = blockIdx.x, warp = threadIdx.x >> 5, lane = threadIdx.x & 31;

    float4 z = {0.f, 0.f, 0.f, 0.f};
    ((float4*)(out + (size_t)t * Hd))[threadIdx.x] = z;

    const float* xr = x + (size_t)t * Hd;
    const float* gr = gw + (size_t)warp * Hd;
    float s = 0.0f;
    for (int h = lane; h < Hd; h += 32) s += xr[h] * gr[h];
    #pragma unroll
    for (int o = 16; o; o >>= 1) s += __shfl_xor_sync(0xFFFFFFFFu, s, o);

    __shared__ float sc[Ed];
    if (lane == 0) sc[warp] = s;
    __syncthreads();
    if (threadIdx.x < Ed && write_logits) out_logits[t * Ed + threadIdx.x] = sc[threadIdx.x];

    if (threadIdx.x == 0) {
        float v[Ed];
        #pragma unroll
        for (int e = 0; e < Ed; e++) v[e] = sc[e];
        int s1 = 0; float m1 = v[0];
        #pragma unroll
        for (int e = 1; e < Ed; e++) if (v[e] > m1) { m1 = v[e]; s1 = e; }
        float Z1 = 0.0f;
        #pragma unroll
        for (int e = 0; e < Ed; e++) {
            float factor = fmaxf(fabsf(v[e]), m1);
            if (!((m1 - v[e]) / factor > 0.02f)) Z1 += expf(v[e] - m1);
        }
        int s2 = -1; float m2 = -INFINITY;
        #pragma unroll
        for (int e = 0; e < Ed; e++) if (e != s1 && v[e] > m2) { m2 = v[e]; s2 = e; }
        float Z2 = 0.0f;
        #pragma unroll
        for (int e = 0; e < Ed; e++) {
            if (e == s1) continue;
            float factor = fmaxf(fabsf(v[e]), m2);
            if (!((m2 - v[e]) / factor > 0.02f)) Z2 += expf(v[e] - m2);
        }
        int p1 = atomicAdd(&g_cnt[s1], 1);
        g_tok[s1 * T + p1] = t;  g_pw[s1 * T + p1] = 1.0f / Z1;
        int p2 = atomicAdd(&g_cnt[s2], 1);
        g_tok[s2 * T + p2] = t;  g_pw[s2 * T + p2] = 1.0f / Z2;
    }
}

// ---------------- kernel 2: ffn1 (fp16 wmma, BK=64) -------------------------
// grid (Fd/BN=32, Ed*8=64), 256 threads (8 warps, 4m x 2n), warp 32x32 dual
__global__ __launch_bounds__(256, 2) void ffn1_kernel()
{
    extern __shared__ char sm[];
    int e   = blockIdx.y >> 3;
    int mt  = blockIdx.y & 7;
    int cnt = g_cnt[e];
    int m0  = mt * BM;
    if (m0 >= cnt) return;
    int f0  = blockIdx.x * BN;

    int* toks = (int*)sm;
    int tid = threadIdx.x;
    if (tid < BM) {
        int i = m0 + tid;
        toks[tid] = (i < cnt) ? g_tok[e * T + i] : g_tok[e * T];
    }
    __syncthreads();

    int arow = tid >> 3;
    int col8 = (tid & 7) * 8;
    uint32_t so = (uint32_t)arow * RB + (tid & 7) * 16;

    const __half* ap0 = g_xh + (size_t)toks[arow     ] * Hd + col8;
    const __half* ap1 = g_xh + (size_t)toks[arow + 32] * Hd + col8;
    const __half* ap2 = g_xh + (size_t)toks[arow + 64] * Hd + col8;
    const __half* ap3 = g_xh + (size_t)toks[arow + 96] * Hd + col8;
    const __half* b1p = g_w1h + (size_t)e * Fd * Hd + (size_t)(f0 + arow) * Hd + col8;
    const __half* b3p = g_w3h + (size_t)e * Fd * Hd + (size_t)(f0 + arow) * Hd + col8;
    const size_t BROW = (size_t)32 * Hd;

    char* smA  = sm + F1_A;
    char* smB1 = sm + F1_B1;
    char* smB3 = sm + F1_B3;

    const int NS = Hd / BK;   // 16
    #pragma unroll
    for (int s = 0; s < NSTAGE - 1; s++) {
        int k0 = s * BK;
        char* A = smA + s * A_BYTES;
        cp16(A + so,           ap0 + k0);
        cp16(A + so + 32 * RB, ap1 + k0);
        cp16(A + so + 64 * RB, ap2 + k0);
        cp16(A + so + 96 * RB, ap3 + k0);
        cp16(smB1 + s * B_BYTES + so,           b1p + k0);
        cp16(smB1 + s * B_BYTES + so + 32 * RB, b1p + BROW + k0);
        cp16(smB3 + s * B_BYTES + so,           b3p + k0);
        cp16(smB3 + s * B_BYTES + so + 32 * RB, b3p + BROW + k0);
        CP_COMMIT();
    }

    wmma::fragment<wmma::matrix_a, 16,16,16, __half, wmma::row_major> fa[2];
    wmma::fragment<wmma::matrix_b, 16,16,16, __half, wmma::col_major> fb1[2], fb3[2];
    wmma::fragment<wmma::accumulator, 16,16,16, float> acc1[2][2], acc3[2][2];
    #pragma unroll
    for (int i = 0; i < 2; i++)
        #pragma unroll
        for (int j = 0; j < 2; j++) { wmma::fill_fragment(acc1[i][j], 0.f); wmma::fill_fragment(acc3[i][j], 0.f); }

    int wid = tid >> 5;
    int wm  = wid >> 1;
    int wn  = wid & 1;

    int cur = 0;
    for (int s = 0; s < NS; s++) {
        CP_WAIT1();
        __syncthreads();
        if (s + 2 < NS) {
            int b2 = (s + 2) % NSTAGE;
            int k0 = (s + 2) * BK;
            char* A = smA + b2 * A_BYTES;
            cp16(A + so,           ap0 + k0);
            cp16(A + so + 32 * RB, ap1 + k0);
            cp16(A + so + 64 * RB, ap2 + k0);
            cp16(A + so + 96 * RB, ap3 + k0);
            cp16(smB1 + b2 * B_BYTES + so,           b1p + k0);
            cp16(smB1 + b2 * B_BYTES + so + 32 * RB, b1p + BROW + k0);
            cp16(smB3 + b2 * B_BYTES + so,           b3p + k0);
            cp16(smB3 + b2 * B_BYTES + so + 32 * RB, b3p + BROW + k0);
        }
        CP_COMMIT();

        const __half* Ab  = (const __half*)(smA  + cur * A_BYTES);
        const __half* B1b = (const __half*)(smB1 + cur * B_BYTES);
        const __half* B3b = (const __half*)(smB3 + cur * B_BYTES);
        #pragma unroll
        for (int ks = 0; ks < BK; ks += 16) {
            wmma::load_matrix_sync(fa[0],  Ab  + (wm*32     ) * KP + ks, KP);
            wmma::load_matrix_sync(fa[1],  Ab  + (wm*32 + 16) * KP + ks, KP);
            wmma::load_matrix_sync(fb1[0], B1b + (wn*32     ) * KP + ks, KP);
            wmma::load_matrix_sync(fb1[1], B1b + (wn*32 + 16) * KP + ks, KP);
            wmma::load_matrix_sync(fb3[0], B3b + (wn*32     ) * KP + ks, KP);
            wmma::load_matrix_sync(fb3[1], B3b + (wn*32 + 16) * KP + ks, KP);
            #pragma unroll
            for (int i = 0; i < 2; i++)
                #pragma unroll
                for (int j = 0; j < 2; j++) {
                    wmma::mma_sync(acc1[i][j], fa[i], fb1[j], acc1[i][j]);
                    wmma::mma_sync(acc3[i][j], fa[i], fb3[j], acc3[i][j]);
                }
        }
        cur = (cur + 1 == NSTAGE) ? 0 : cur + 1;
    }

    __syncthreads();
    float* pool = (float*)(sm + F1_A);
    #pragma unroll
    for (int i = 0; i < 2; i++)
        #pragma unroll
        for (int j = 0; j < 2; j++) {
            #pragma unroll
            for (int el = 0; el < acc1[i][j].num_elements; el++) {
                float h1 = acc1[i][j].x[el], h3 = acc3[i][j].x[el];
                acc1[i][j].x[el] = h1 / (1.0f + expf(-h1)) * h3;
            }
            wmma::store_matrix_sync(
                pool + (size_t)(wm*32 + i*16) * OPAD + wn*32 + j*16,
                acc1[i][j], OPAD, wmma::mem_row_major);
        }
    __syncthreads();

    for (int idx = tid; idx < BM * BN / 2; idx += 256) {
        int r  = idx >> 5;
        int c2 = idx & 31;
        uint32_t h = f2h2(pool[r * OPAD + 2*c2], pool[r * OPAD + 2*c2 + 1]);
        *(uint32_t*)&g_interh[((size_t)e * T + m0 + r) * Fd + f0 + 2*c2] = h;
    }
}

// ---------------- kernel 3: ffn2 (fp16 wmma, BK=64, 2-way K-split) ----------
// grid (Hd/BN=16, Ed*8=64, 2), 256 threads, warp 32x32
#define KSPLIT 2
#define KHALF (Fd / KSPLIT)    // 1024
__global__ __launch_bounds__(256, 2) void ffn2_kernel(float* __restrict__ out)
{
    extern __shared__ char sm[];
    int e   = blockIdx.y >> 3;
    int mt  = blockIdx.y & 7;
    int cnt = g_cnt[e];
    int m0  = mt * BM;
    if (m0 >= cnt) return;
    int h0  = blockIdx.x * BN;
    int kz  = blockIdx.z * KHALF;

    int*   toks = (int*)sm;
    float* pws  = (float*)(sm + 512);
    int tid = threadIdx.x;
    if (tid < BM) {
        int i = m0 + tid;
        toks[tid] = (i < cnt) ? g_tok[e * T + i] : 0;
        pws [tid] = (i < cnt) ? g_pw [e * T + i] : 0.0f;
    }
    __syncthreads();

    int arow = tid >> 3;
    int col8 = (tid & 7) * 8;
    uint32_t so = (uint32_t)arow * RB + (tid & 7) * 16;

    const __half* ag = &g_interh[((size_t)e * T + m0 + arow) * Fd + kz + col8];
    const __half* bg = g_w2h + ((size_t)e * Hd + h0 + arow) * Fd + kz + col8;
    const size_t AROW = (size_t)32 * Fd;

    char* smA = sm + F2_A;
    char* smB = sm + F2_B;

    const int NS = KHALF / BK;   // 16
    #pragma unroll
    for (int s = 0; s < NSTAGE - 1; s++) {
        int k0 = s * BK;
        char* A = smA + s * A_BYTES;
        cp16(A + so,           ag + k0);
        cp16(A + so + 32 * RB, ag + AROW + k0);
        cp16(A + so + 64 * RB, ag + 2 * AROW + k0);
        cp16(A + so + 96 * RB, ag + 3 * AROW + k0);
        cp16(smB + s * B_BYTES + so,           bg + k0);
        cp16(smB + s * B_BYTES + so + 32 * RB, bg + AROW + k0);
        CP_COMMIT();
    }

    wmma::fragment<wmma::matrix_a, 16,16,16, __half, wmma::row_major> fa[2];
    wmma::fragment<wmma::matrix_b, 16,16,16, __half, wmma::col_major> fb[2];
    wmma::fragment<wmma::accumulator, 16,16,16, float> acc[2][2];
    #pragma unroll
    for (int i = 0; i < 2; i++)
        #pragma unroll
        for (int j = 0; j < 2; j++) wmma::fill_fragment(acc[i][j], 0.f);

    int wid = tid >> 5;
    int wm  = wid >> 1;
    int wn  = wid & 1;

    int cur = 0;
    for (int s = 0; s < NS; s++) {
        CP_WAIT1();
        __syncthreads();
        if (s + 2 < NS) {
            int b2 = (s + 2) % NSTAGE;
            int k0 = (s + 2) * BK;
            char* A = smA + b2 * A_BYTES;
            cp16(A + so,           ag + k0);
            cp16(A + so + 32 * RB, ag + AROW + k0);
            cp16(A + so + 64 * RB, ag + 2 * AROW + k0);
            cp16(A + so + 96 * RB, ag + 3 * AROW + k0);
            cp16(smB + b2 * B_BYTES + so,           bg + k0);
            cp16(smB + b2 * B_BYTES + so + 32 * RB, bg + AROW + k0);
        }
        CP_COMMIT();

        const __half* Ab = (const __half*)(smA + cur * A_BYTES);
        const __half* Bb = (const __half*)(smB + cur * B_BYTES);
        #pragma unroll
        for (int ks = 0; ks < BK; ks += 16) {
            wmma::load_matrix_sync(fa[0], Ab + (wm*32     ) * KP + ks, KP);
            wmma::load_matrix_sync(fa[1], Ab + (wm*32 + 16) * KP + ks, KP);
            wmma::load_matrix_sync(fb[0], Bb + (wn*32     ) * KP + ks, KP);
            wmma::load_matrix_sync(fb[1], Bb + (wn*32 + 16) * KP + ks, KP);
            #pragma unroll
            for (int i = 0; i < 2; i++)
                #pragma unroll
                for (int j = 0; j < 2; j++)
                    wmma::mma_sync(acc[i][j], fa[i], fb[j], acc[i][j]);
        }
        cur = (cur + 1 == NSTAGE) ? 0 : cur + 1;
    }

    __syncthreads();
    float* pool = (float*)(sm + F2_A);
    #pragma unroll
    for (int i = 0; i < 2; i++)
        #pragma unroll
        for (int j = 0; j < 2; j++)
            wmma::store_matrix_sync(
                pool + (size_t)(wm*32 + i*16) * OPAD + wn*32 + j*16,
                acc[i][j], OPAD, wmma::mem_row_major);
    __syncthreads();

    for (int idx = tid; idx < BM * BN; idx += 256) {
        int r = idx >> 6;
        int c = idx & 63;
        if (m0 + r < cnt)
            atomicAdd(&out[(size_t)toks[r] * Hd + h0 + c], pws[r] * pool[r * OPAD + c]);
    }
}

// ---------------- launch ----------------
extern "C" void kernel_launch(void* const* d_in, const int* in_sizes, int n_in,
                              void* d_out, int out_size)
{
    const float* x  = (const float*)d_in[0];
    const float* gw = (const float*)d_in[1];
    const float* w1 = (const float*)d_in[2];
    const float* w2 = (const float*)d_in[3];
    const float* w3 = (const float*)d_in[4];
    float* out = (float*)d_out;

    cudaFuncSetAttribute(ffn1_kernel, cudaFuncAttributeMaxDynamicSharedMemorySize, SMEM_FFN1);
    cudaFuncSetAttribute(ffn2_kernel, cudaFuncAttributeMaxDynamicSharedMemorySize, SMEM_FFN2);

    int write_logits = (out_size >= T * Hd + T * Ed) ? 1 : 0;
    float* out_logits = out + (size_t)T * Hd;

    void *d_w1h, *d_w3h, *d_w2h, *d_xh;
    cudaGetSymbolAddress(&d_w1h, g_w1h);
    cudaGetSymbolAddress(&d_w3h, g_w3h);
    cudaGetSymbolAddress(&d_w2h, g_w2h);
    cudaGetSymbolAddress(&d_xh,  g_xh);

    // side stream + events for overlapping the w2 convert with ffn1
    static cudaStream_t side = nullptr;
    static cudaEvent_t evFork = nullptr, evJoin = nullptr;
    if (!side) {
        cudaStreamCreateWithFlags(&side, cudaStreamNonBlocking);
        cudaEventCreateWithFlags(&evFork, cudaEventDisableTiming);
        cudaEventCreateWithFlags(&evJoin, cudaEventDisableTiming);
    }

    // main stream: converts needed by ffn1 (+ counter reset), then router
    cvt_w13x_kernel<<<2 * WSEG + XSEG, 256>>>(
        (const float4*)w1, (const float4*)w3, (const float4*)x,
        (uint4*)d_w1h, (uint4*)d_w3h, (uint4*)d_xh);

    router_kernel<<<T, 256>>>(x, gw, out, out_logits, write_logits);

    // fork: w2 convert runs on side stream, concurrent with ffn1
    cudaEventRecord(evFork, 0);
    cudaStreamWaitEvent(side, evFork, 0);
    cvt_w2_kernel<<<WSEG, 256, 0, side>>>((const float4*)w2, (uint4*)d_w2h);
    cudaEventRecord(evJoin, side);

    dim3 g1(Fd / BN, Ed * 8);
    ffn1_kernel<<<g1, 256, SMEM_FFN1>>>();

    // join: ffn2 needs w2h
    cudaStreamWaitEvent(0, evJoin, 0);
    dim3 g2(Hd / BN, Ed * 8, KSPLIT);
    ffn2_kernel<<<g2, 256, SMEM_FFN2>>>(out);
}

// round 13
// speedup vs baseline: 1.4690x; 1.0122x over previous
#include <cuda_runtime.h>
#include <cuda_fp16.h>
#include <mma.h>
#include <math.h>
#include <stdint.h>

using namespace nvcuda;

#define T  1024
#define Hd 1024
#define Fd 2048
#define Ed 8

#define BM 128
#define BN 64
#define BK 64                  // halves per stage; 128B data per row
#define KP 72                  // BK + 8 pad halves -> 144B rows
#define RB 144
#define A_BYTES (BM * RB)      // 18432
#define B_BYTES (BN * RB)      // 9216
#define NSTAGE 3
#define OPAD 68

#define F1_A   1024
#define F1_B1  (F1_A  + NSTAGE * A_BYTES)
#define F1_B3  (F1_B1 + NSTAGE * B_BYTES)
#define SMEM_FFN1 (F1_B3 + NSTAGE * B_BYTES)  // 111616
#define F2_A   1024
#define F2_B   (F2_A + NSTAGE * A_BYTES)
#define SMEM_FFN2 (F2_B + NSTAGE * B_BYTES)   // 83968

// ---------------- scratch ----------------
__device__ __half g_interh[(size_t)Ed * T * Fd];
__device__ __half g_w1h[(size_t)Ed * Fd * Hd];
__device__ __half g_w3h[(size_t)Ed * Fd * Hd];
__device__ __half g_w2h[(size_t)Ed * Hd * Fd];
__device__ __half g_xh[(size_t)T * Hd];
__device__ int   g_tok[Ed * T];
__device__ float g_pw[Ed * T];
__device__ int   g_cnt[Ed];

#define WSEG 8192   // blocks per weight segment

__device__ __forceinline__ uint32_t f2h2(float x, float y) {
    __half2 h = __floats2half2_rn(x, y);
    return *(uint32_t*)&h;
}
__device__ __forceinline__ void cp16(void* s, const void* g) {
    unsigned a = (unsigned)__cvta_generic_to_shared(s);
    asm volatile("cp.async.cg.shared.global [%0], [%1], 16;" :: "r"(a), "l"(g));
}
#define CP_COMMIT() asm volatile("cp.async.commit_group;" ::)
#define CP_WAIT1()  asm volatile("cp.async.wait_group 1;" ::)

// ---------------- kernel 0: counter reset (main stream, precedes router) ---
__global__ void reset_kernel() {
    if (threadIdx.x < Ed) g_cnt[threadIdx.x] = 0;
}

// ---------------- kernel 0a: w1/w3 converts (side stream) ------------------
__global__ __launch_bounds__(256) void cvt_w13_kernel(
    const float4* __restrict__ w1, const float4* __restrict__ w3,
    uint4* __restrict__ d1, uint4* __restrict__ d3)
{
    int b = blockIdx.x;
    const float4* src;
    uint4* dst;
    size_t base;
    if (b < WSEG) { src = w1; dst = d1; base = (size_t)b * 256; }
    else          { src = w3; dst = d3; base = (size_t)(b - WSEG) * 256; }

    size_t i = base + threadIdx.x;
    float4 a = src[2 * i];
    float4 c = src[2 * i + 1];
    uint4 o;
    o.x = f2h2(a.x, a.y); o.y = f2h2(a.z, a.w);
    o.z = f2h2(c.x, c.y); o.w = f2h2(c.z, c.w);
    dst[i] = o;
}

// ---------------- kernel 0b: w2 convert (side stream, overlaps ffn1) -------
__global__ __launch_bounds__(256) void cvt_w2_kernel(
    const float4* __restrict__ w2, uint4* __restrict__ d2)
{
    size_t i = (size_t)blockIdx.x * 256 + threadIdx.x;
    float4 a = w2[2 * i];
    float4 c = w2[2 * i + 1];
    uint4 o;
    o.x = f2h2(a.x, a.y); o.y = f2h2(a.z, a.w);
    o.z = f2h2(c.x, c.y); o.w = f2h2(c.z, c.w);
    d2[i] = o;
}

// ---------------- kernel 1: router + out-zero + x->fp16 + inline scatter ---
__global__ __launch_bounds__(256) void router_kernel(
    const float* __restrict__ x, const float* __restrict__ gw,
    float* __restrict__ out, float* __restrict__ out_logits, int write_logits)
{
    int t = blockIdx.x, warp = threadIdx.x >> 5, lane = threadIdx.x & 31;

    // zero this token's output row + convert this token's x row to fp16
    float4 z = {0.f, 0.f, 0.f, 0.f};
    ((float4*)(out + (size_t)t * Hd))[threadIdx.x] = z;
    {
        float4 v = ((const float4*)(x + (size_t)t * Hd))[threadIdx.x];
        uint2 o = { f2h2(v.x, v.y), f2h2(v.z, v.w) };
        ((uint2*)(g_xh + (size_t)t * Hd))[threadIdx.x] = o;
    }

    const float* xr = x + (size_t)t * Hd;
    const float* gr = gw + (size_t)warp * Hd;
    float s = 0.0f;
    for (int h = lane; h < Hd; h += 32) s += xr[h] * gr[h];
    #pragma unroll
    for (int o = 16; o; o >>= 1) s += __shfl_xor_sync(0xFFFFFFFFu, s, o);

    __shared__ float sc[Ed];
    if (lane == 0) sc[warp] = s;
    __syncthreads();
    if (threadIdx.x < Ed && write_logits) out_logits[t * Ed + threadIdx.x] = sc[threadIdx.x];

    if (threadIdx.x == 0) {
        float v[Ed];
        #pragma unroll
        for (int e = 0; e < Ed; e++) v[e] = sc[e];
        int s1 = 0; float m1 = v[0];
        #pragma unroll
        for (int e = 1; e < Ed; e++) if (v[e] > m1) { m1 = v[e]; s1 = e; }
        float Z1 = 0.0f;
        #pragma unroll
        for (int e = 0; e < Ed; e++) {
            float factor = fmaxf(fabsf(v[e]), m1);
            if (!((m1 - v[e]) / factor > 0.02f)) Z1 += expf(v[e] - m1);
        }
        int s2 = -1; float m2 = -INFINITY;
        #pragma unroll
        for (int e = 0; e < Ed; e++) if (e != s1 && v[e] > m2) { m2 = v[e]; s2 = e; }
        float Z2 = 0.0f;
        #pragma unroll
        for (int e = 0; e < Ed; e++) {
            if (e == s1) continue;
            float factor = fmaxf(fabsf(v[e]), m2);
            if (!((m2 - v[e]) / factor > 0.02f)) Z2 += expf(v[e] - m2);
        }
        int p1 = atomicAdd(&g_cnt[s1], 1);
        g_tok[s1 * T + p1] = t;  g_pw[s1 * T + p1] = 1.0f / Z1;
        int p2 = atomicAdd(&g_cnt[s2], 1);
        g_tok[s2 * T + p2] = t;  g_pw[s2 * T + p2] = 1.0f / Z2;
    }
}

// ---------------- kernel 2: ffn1 (fp16 wmma, BK=64) -------------------------
// grid (Fd/BN=32, Ed*8=64), 256 threads (8 warps, 4m x 2n), warp 32x32 dual
__global__ __launch_bounds__(256, 2) void ffn1_kernel()
{
    extern __shared__ char sm[];
    int e   = blockIdx.y >> 3;
    int mt  = blockIdx.y & 7;
    int cnt = g_cnt[e];
    int m0  = mt * BM;
    if (m0 >= cnt) return;
    int f0  = blockIdx.x * BN;

    int* toks = (int*)sm;
    int tid = threadIdx.x;
    if (tid < BM) {
        int i = m0 + tid;
        toks[tid] = (i < cnt) ? g_tok[e * T + i] : g_tok[e * T];
    }
    __syncthreads();

    int arow = tid >> 3;
    int col8 = (tid & 7) * 8;
    uint32_t so = (uint32_t)arow * RB + (tid & 7) * 16;

    const __half* ap0 = g_xh + (size_t)toks[arow     ] * Hd + col8;
    const __half* ap1 = g_xh + (size_t)toks[arow + 32] * Hd + col8;
    const __half* ap2 = g_xh + (size_t)toks[arow + 64] * Hd + col8;
    const __half* ap3 = g_xh + (size_t)toks[arow + 96] * Hd + col8;
    const __half* b1p = g_w1h + (size_t)e * Fd * Hd + (size_t)(f0 + arow) * Hd + col8;
    const __half* b3p = g_w3h + (size_t)e * Fd * Hd + (size_t)(f0 + arow) * Hd + col8;
    const size_t BROW = (size_t)32 * Hd;

    char* smA  = sm + F1_A;
    char* smB1 = sm + F1_B1;
    char* smB3 = sm + F1_B3;

    const int NS = Hd / BK;   // 16
    #pragma unroll
    for (int s = 0; s < NSTAGE - 1; s++) {
        int k0 = s * BK;
        char* A = smA + s * A_BYTES;
        cp16(A + so,           ap0 + k0);
        cp16(A + so + 32 * RB, ap1 + k0);
        cp16(A + so + 64 * RB, ap2 + k0);
        cp16(A + so + 96 * RB, ap3 + k0);
        cp16(smB1 + s * B_BYTES + so,           b1p + k0);
        cp16(smB1 + s * B_BYTES + so + 32 * RB, b1p + BROW + k0);
        cp16(smB3 + s * B_BYTES + so,           b3p + k0);
        cp16(smB3 + s * B_BYTES + so + 32 * RB, b3p + BROW + k0);
        CP_COMMIT();
    }

    wmma::fragment<wmma::matrix_a, 16,16,16, __half, wmma::row_major> fa[2];
    wmma::fragment<wmma::matrix_b, 16,16,16, __half, wmma::col_major> fb1[2], fb3[2];
    wmma::fragment<wmma::accumulator, 16,16,16, float> acc1[2][2], acc3[2][2];
    #pragma unroll
    for (int i = 0; i < 2; i++)
        #pragma unroll
        for (int j = 0; j < 2; j++) { wmma::fill_fragment(acc1[i][j], 0.f); wmma::fill_fragment(acc3[i][j], 0.f); }

    int wid = tid >> 5;
    int wm  = wid >> 1;
    int wn  = wid & 1;

    int cur = 0;
    for (int s = 0; s < NS; s++) {
        CP_WAIT1();
        __syncthreads();
        if (s + 2 < NS) {
            int b2 = (s + 2) % NSTAGE;
            int k0 = (s + 2) * BK;
            char* A = smA + b2 * A_BYTES;
            cp16(A + so,           ap0 + k0);
            cp16(A + so + 32 * RB, ap1 + k0);
            cp16(A + so + 64 * RB, ap2 + k0);
            cp16(A + so + 96 * RB, ap3 + k0);
            cp16(smB1 + b2 * B_BYTES + so,           b1p + k0);
            cp16(smB1 + b2 * B_BYTES + so + 32 * RB, b1p + BROW + k0);
            cp16(smB3 + b2 * B_BYTES + so,           b3p + k0);
            cp16(smB3 + b2 * B_BYTES + so + 32 * RB, b3p + BROW + k0);
        }
        CP_COMMIT();

        const __half* Ab  = (const __half*)(smA  + cur * A_BYTES);
        const __half* B1b = (const __half*)(smB1 + cur * B_BYTES);
        const __half* B3b = (const __half*)(smB3 + cur * B_BYTES);
        #pragma unroll
        for (int ks = 0; ks < BK; ks += 16) {
            wmma::load_matrix_sync(fa[0],  Ab  + (wm*32     ) * KP + ks, KP);
            wmma::load_matrix_sync(fa[1],  Ab  + (wm*32 + 16) * KP + ks, KP);
            wmma::load_matrix_sync(fb1[0], B1b + (wn*32     ) * KP + ks, KP);
            wmma::load_matrix_sync(fb1[1], B1b + (wn*32 + 16) * KP + ks, KP);
            wmma::load_matrix_sync(fb3[0], B3b + (wn*32     ) * KP + ks, KP);
            wmma::load_matrix_sync(fb3[1], B3b + (wn*32 + 16) * KP + ks, KP);
            #pragma unroll
            for (int i = 0; i < 2; i++)
                #pragma unroll
                for (int j = 0; j < 2; j++) {
                    wmma::mma_sync(acc1[i][j], fa[i], fb1[j], acc1[i][j]);
                    wmma::mma_sync(acc3[i][j], fa[i], fb3[j], acc3[i][j]);
                }
        }
        cur = (cur + 1 == NSTAGE) ? 0 : cur + 1;
    }

    __syncthreads();
    float* pool = (float*)(sm + F1_A);
    #pragma unroll
    for (int i = 0; i < 2; i++)
        #pragma unroll
        for (int j = 0; j < 2; j++) {
            #pragma unroll
            for (int el = 0; el < acc1[i][j].num_elements; el++) {
                float h1 = acc1[i][j].x[el], h3 = acc3[i][j].x[el];
                acc1[i][j].x[el] = h1 / (1.0f + expf(-h1)) * h3;
            }
            wmma::store_matrix_sync(
                pool + (size_t)(wm*32 + i*16) * OPAD + wn*32 + j*16,
                acc1[i][j], OPAD, wmma::mem_row_major);
        }
    __syncthreads();

    for (int idx = tid; idx < BM * BN / 2; idx += 256) {
        int r  = idx >> 5;
        int c2 = idx & 31;
        uint32_t h = f2h2(pool[r * OPAD + 2*c2], pool[r * OPAD + 2*c2 + 1]);
        *(uint32_t*)&g_interh[((size_t)e * T + m0 + r) * Fd + f0 + 2*c2] = h;
    }
}

// ---------------- kernel 3: ffn2 (fp16 wmma, BK=64, 2-way K-split) ----------
#define KSPLIT 2
#define KHALF (Fd / KSPLIT)    // 1024
__global__ __launch_bounds__(256, 2) void ffn2_kernel(float* __restrict__ out)
{
    extern __shared__ char sm[];
    int e   = blockIdx.y >> 3;
    int mt  = blockIdx.y & 7;
    int cnt = g_cnt[e];
    int m0  = mt * BM;
    if (m0 >= cnt) return;
    int h0  = blockIdx.x * BN;
    int kz  = blockIdx.z * KHALF;

    int*   toks = (int*)sm;
    float* pws  = (float*)(sm + 512);
    int tid = threadIdx.x;
    if (tid < BM) {
        int i = m0 + tid;
        toks[tid] = (i < cnt) ? g_tok[e * T + i] : 0;
        pws [tid] = (i < cnt) ? g_pw [e * T + i] : 0.0f;
    }
    __syncthreads();

    int arow = tid >> 3;
    int col8 = (tid & 7) * 8;
    uint32_t so = (uint32_t)arow * RB + (tid & 7) * 16;

    const __half* ag = &g_interh[((size_t)e * T + m0 + arow) * Fd + kz + col8];
    const __half* bg = g_w2h + ((size_t)e * Hd + h0 + arow) * Fd + kz + col8;
    const size_t AROW = (size_t)32 * Fd;

    char* smA = sm + F2_A;
    char* smB = sm + F2_B;

    const int NS = KHALF / BK;   // 16
    #pragma unroll
    for (int s = 0; s < NSTAGE - 1; s++) {
        int k0 = s * BK;
        char* A = smA + s * A_BYTES;
        cp16(A + so,           ag + k0);
        cp16(A + so + 32 * RB, ag + AROW + k0);
        cp16(A + so + 64 * RB, ag + 2 * AROW + k0);
        cp16(A + so + 96 * RB, ag + 3 * AROW + k0);
        cp16(smB + s * B_BYTES + so,           bg + k0);
        cp16(smB + s * B_BYTES + so + 32 * RB, bg + AROW + k0);
        CP_COMMIT();
    }

    wmma::fragment<wmma::matrix_a, 16,16,16, __half, wmma::row_major> fa[2];
    wmma::fragment<wmma::matrix_b, 16,16,16, __half, wmma::col_major> fb[2];
    wmma::fragment<wmma::accumulator, 16,16,16, float> acc[2][2];
    #pragma unroll
    for (int i = 0; i < 2; i++)
        #pragma unroll
        for (int j = 0; j < 2; j++) wmma::fill_fragment(acc[i][j], 0.f);

    int wid = tid >> 5;
    int wm  = wid >> 1;
    int wn  = wid & 1;

    int cur = 0;
    for (int s = 0; s < NS; s++) {
        CP_WAIT1();
        __syncthreads();
        if (s + 2 < NS) {
            int b2 = (s + 2) % NSTAGE;
            int k0 = (s + 2) * BK;
            char* A = smA + b2 * A_BYTES;
            cp16(A + so,           ag + k0);
            cp16(A + so + 32 * RB, ag + AROW + k0);
            cp16(A + so + 64 * RB, ag + 2 * AROW + k0);
            cp16(A + so + 96 * RB, ag + 3 * AROW + k0);
            cp16(smB + b2 * B_BYTES + so,           bg + k0);
            cp16(smB + b2 * B_BYTES + so + 32 * RB, bg + AROW + k0);
        }
        CP_COMMIT();

        const __half* Ab = (const __half*)(smA + cur * A_BYTES);
        const __half* Bb = (const __half*)(smB + cur * B_BYTES);
        #pragma unroll
        for (int ks = 0; ks < BK; ks += 16) {
            wmma::load_matrix_sync(fa[0], Ab + (wm*32     ) * KP + ks, KP);
            wmma::load_matrix_sync(fa[1], Ab + (wm*32 + 16) * KP + ks, KP);
            wmma::load_matrix_sync(fb[0], Bb + (wn*32     ) * KP + ks, KP);
            wmma::load_matrix_sync(fb[1], Bb + (wn*32 + 16) * KP + ks, KP);
            #pragma unroll
            for (int i = 0; i < 2; i++)
                #pragma unroll
                for (int j = 0; j < 2; j++)
                    wmma::mma_sync(acc[i][j], fa[i], fb[j], acc[i][j]);
        }
        cur = (cur + 1 == NSTAGE) ? 0 : cur + 1;
    }

    __syncthreads();
    float* pool = (float*)(sm + F2_A);
    #pragma unroll
    for (int i = 0; i < 2; i++)
        #pragma unroll
        for (int j = 0; j < 2; j++)
            wmma::store_matrix_sync(
                pool + (size_t)(wm*32 + i*16) * OPAD + wn*32 + j*16,
                acc[i][j], OPAD, wmma::mem_row_major);
    __syncthreads();

    for (int idx = tid; idx < BM * BN; idx += 256) {
        int r = idx >> 6;
        int c = idx & 63;
        if (m0 + r < cnt)
            atomicAdd(&out[(size_t)toks[r] * Hd + h0 + c], pws[r] * pool[r * OPAD + c]);
    }
}

// ---------------- launch ----------------
extern "C" void kernel_launch(void* const* d_in, const int* in_sizes, int n_in,
                              void* d_out, int out_size)
{
    const float* x  = (const float*)d_in[0];
    const float* gw = (const float*)d_in[1];
    const float* w1 = (const float*)d_in[2];
    const float* w2 = (const float*)d_in[3];
    const float* w3 = (const float*)d_in[4];
    float* out = (float*)d_out;

    cudaFuncSetAttribute(ffn1_kernel, cudaFuncAttributeMaxDynamicSharedMemorySize, SMEM_FFN1);
    cudaFuncSetAttribute(ffn2_kernel, cudaFuncAttributeMaxDynamicSharedMemorySize, SMEM_FFN2);

    int write_logits = (out_size >= T * Hd + T * Ed) ? 1 : 0;
    float* out_logits = out + (size_t)T * Hd;

    void *d_w1h, *d_w3h, *d_w2h;
    cudaGetSymbolAddress(&d_w1h, g_w1h);
    cudaGetSymbolAddress(&d_w3h, g_w3h);
    cudaGetSymbolAddress(&d_w2h, g_w2h);

    static cudaStream_t side = nullptr;
    static cudaEvent_t evFork = nullptr, evW13 = nullptr, evW2 = nullptr;
    if (!side) {
        cudaStreamCreateWithFlags(&side, cudaStreamNonBlocking);
        cudaEventCreateWithFlags(&evFork, cudaEventDisableTiming);
        cudaEventCreateWithFlags(&evW13, cudaEventDisableTiming);
        cudaEventCreateWithFlags(&evW2, cudaEventDisableTiming);
    }

    // fork: weight converts run on side stream from the very start
    cudaEventRecord(evFork, 0);
    cudaStreamWaitEvent(side, evFork, 0);
    cvt_w13_kernel<<<2 * WSEG, 256, 0, side>>>(
        (const float4*)w1, (const float4*)w3, (uint4*)d_w1h, (uint4*)d_w3h);
    cudaEventRecord(evW13, side);
    cvt_w2_kernel<<<WSEG, 256, 0, side>>>((const float4*)w2, (uint4*)d_w2h);
    cudaEventRecord(evW2, side);

    // main: reset -> router (overlaps cvt_w13) -> ffn1 -> ffn2
    reset_kernel<<<1, 32>>>();
    router_kernel<<<T, 256>>>(x, gw, out, out_logits, write_logits);

    cudaStreamWaitEvent(0, evW13, 0);
    dim3 g1(Fd / BN, Ed * 8);
    ffn1_kernel<<<g1, 256, SMEM_FFN1>>>();

    cudaStreamWaitEvent(0, evW2, 0);
    dim3 g2(Hd / BN, Ed * 8, KSPLIT);
    ffn2_kernel<<<g2, 256, SMEM_FFN2>>>(out);
}